// round 12
// baseline (speedup 1.0000x reference)
#include <cuda_runtime.h>
#include <cuda_fp16.h>
#include <cstdint>

#define EMBED    768
#define HEADS    6
#define HEAD_DIM 256
#define SEQ      128
#define BATCH    512
#define NTOK     (BATCH * SEQ)        // 65536
#define CATD     (HEADS * HEAD_DIM)   // 1536
#define QKVD     (3 * CATD)           // 4608
#define FFN      (4 * EMBED)          // 3072

// ================= helpers =================
__device__ __forceinline__ uint32_t packh2(float lo, float hi) {
    uint32_t r;
    asm("cvt.rn.f16x2.f32 %0, %1, %2;" : "=r"(r) : "f"(hi), "f"(lo));
    return r;
}
__device__ __forceinline__ void mma16816(float* c, const uint32_t* a, const uint32_t* b) {
    asm volatile(
        "mma.sync.aligned.m16n8k16.row.col.f32.f16.f16.f32 "
        "{%0,%1,%2,%3}, {%4,%5,%6,%7}, {%8,%9}, {%0,%1,%2,%3};"
        : "+f"(c[0]), "+f"(c[1]), "+f"(c[2]), "+f"(c[3])
        : "r"(a[0]), "r"(a[1]), "r"(a[2]), "r"(a[3]), "r"(b[0]), "r"(b[1]));
}
__device__ __forceinline__ uint32_t smem_u32(const void* p) {
    uint32_t a;
    asm("{ .reg .u64 t; cvta.to.shared.u64 t, %1; cvt.u32.u64 %0, t; }" : "=r"(a) : "l"(p));
    return a;
}
#define CP_ASYNC16(saddr, gptr) \
    asm volatile("cp.async.cg.shared.global [%0], [%1], 16;" :: "r"(saddr), "l"(gptr))
#define CP_COMMIT() asm volatile("cp.async.commit_group;" ::: "memory")
#define CP_WAIT2()  asm volatile("cp.async.wait_group 2;" ::: "memory")
#define LDSM_X4(r0, r1, r2, r3, addr) \
    asm volatile("ldmatrix.sync.aligned.m8n8.x4.shared.b16 {%0,%1,%2,%3}, [%4];" \
        : "=r"(r0), "=r"(r1), "=r"(r2), "=r"(r3) : "r"(addr))

// GEMM tiling
#define TILE_NF  128
#define TILE_TK  256
#define KCH      64
#define HSTR     72                                    // halves per smem row (64 + 8 pad)
#define STAGES   4
#define STG_H    ((TILE_TK + TILE_NF) * HSTR)          // halves per stage
#define STG_B    (STG_H * 2)                           // bytes per stage (55296)
#define GEMM_SMEM (STAGES * STG_B)                     // 221184 B

// ================= scratch =================
__device__ __half g_hh  [(size_t)NTOK * EMBED];
__device__ __half g_qkv [(size_t)NTOK * QKVD];
__device__ __half g_oh  [(size_t)NTOK * CATD];
__device__ float  g_res [(size_t)NTOK * EMBED];
__device__ __half g_mid [(size_t)NTOK * FFN];
__device__ __half g_wqkv[(size_t)QKVD * EMBED];
__device__ __half g_wto [(size_t)EMBED * CATD];
__device__ __half g_wt1 [(size_t)FFN * EMBED];
__device__ __half g_wt2 [(size_t)EMBED * FFN];

// ================= transpose: in(k, n) -> out[n][k] (fp16 out) =================
__global__ __launch_bounds__(256) void transpose_k(
    const float* __restrict__ in, __half* __restrict__ out, int Kdim, int N, int Dh)
{
    __shared__ float t[32][33];
    const int k0 = blockIdx.y * 32;
    const int n0 = blockIdx.x * 32;
    const int tx = threadIdx.x, ty = threadIdx.y;

    #pragma unroll
    for (int i = 0; i < 4; i++) {
        const int k = k0 + ty + 8 * i;
        const int n = n0 + tx;
        const int h = n / Dh, d = n - h * Dh;
        t[ty + 8 * i][tx] = in[(size_t)h * Kdim * Dh + (size_t)k * Dh + d];
    }
    __syncthreads();
    #pragma unroll
    for (int i = 0; i < 4; i++) {
        out[(size_t)(n0 + ty + 8 * i) * Kdim + k0 + tx] = __float2half_rn(t[tx][ty + 8 * i]);
    }
}

// ================= LayerNorm (fp32 in -> fp16 out) =================
__global__ __launch_bounds__(256) void layernorm_k(
    const float* __restrict__ x, __half* __restrict__ y,
    const float* __restrict__ g, const float* __restrict__ b)
{
    const int row = blockIdx.x;
    const int tid = threadIdx.x;
    const float* xr = x + (size_t)row * EMBED;

    float v0 = xr[tid];
    float v1 = xr[tid + 256];
    float v2 = xr[tid + 512];

    float s = v0 + v1 + v2;
    float q = v0 * v0 + v1 * v1 + v2 * v2;

    #pragma unroll
    for (int o = 16; o; o >>= 1) {
        s += __shfl_xor_sync(0xffffffffu, s, o);
        q += __shfl_xor_sync(0xffffffffu, q, o);
    }
    __shared__ float ss[8], sq[8];
    const int w = tid >> 5, l = tid & 31;
    if (l == 0) { ss[w] = s; sq[w] = q; }
    __syncthreads();
    float S = 0.f, Q = 0.f;
    #pragma unroll
    for (int i = 0; i < 8; i++) { S += ss[i]; Q += sq[i]; }

    const float mu  = S * (1.0f / EMBED);
    const float var = Q * (1.0f / EMBED) - mu * mu;
    const float inv = rsqrtf(var + 1e-5f);

    __half* yr = y + (size_t)row * EMBED;
    yr[tid]       = __float2half_rn((v0 - mu) * inv * g[tid]       + b[tid]);
    yr[tid + 256] = __float2half_rn((v1 - mu) * inv * g[tid + 256] + b[tid + 256]);
    yr[tid + 512] = __float2half_rn((v2 - mu) * inv * g[tid + 512] + b[tid + 512]);
}

// ================= GEMM (fp16, 4-stage cp.async, ldmatrix) =================
// C[m,n] = sum_k Hm[m,k]*Wt[n,k] (+bias)(relu)(+res)
template<bool OUT16, bool BIAS, bool RELU, bool RES>
__global__ __launch_bounds__(256) void gemm_tc(
    const __half* __restrict__ Wt,   // [Nout, K]  K-major fp16
    const __half* __restrict__ Hm,   // [NTOK, K]  fp16
    void* __restrict__ Cout,         // fp16 or fp32 [NTOK, Nout]
    int K, int Nout,
    const float* __restrict__ bias,
    const float* __restrict__ res)
{
    extern __shared__ char smem[];
    const uint32_t sb32 = smem_u32(smem);

    const int tid = threadIdx.x;
    const int wid = tid >> 5, lid = tid & 31;
    const int g = lid >> 2, t = lid & 3;
    const int wm = wid & 3;
    const int wn = wid >> 2;

    const int n0 = blockIdx.x * TILE_NF;
    const int m0 = blockIdx.y * TILE_TK;
    const int chunks = K / KCH;   // >= 12 for all our shapes

    const __half* Ag = Hm + (size_t)m0 * K;
    const __half* Bg = Wt + (size_t)n0 * K;

    const int arow = tid >> 3, aq = tid & 7;

    const uint32_t a_lane = (uint32_t)(((lid & 15) * HSTR + ((lid >> 4) << 3)) * 2);
    const uint32_t b_lane = (uint32_t)((((lid & 7) + ((lid >> 4) << 3)) * HSTR + ((lid >> 3) & 1) * 8) * 2);

    float acc[4][8][4];
    #pragma unroll
    for (int i = 0; i < 4; i++)
        #pragma unroll
        for (int j = 0; j < 8; j++)
            #pragma unroll
            for (int r = 0; r < 4; r++) acc[i][j][r] = 0.f;

    #define ISSUE_CHUNK(chunk, stg) do { \
        const int kofs_ = (chunk) * KCH; \
        const uint32_t sA_ = sb32 + (stg) * STG_B; \
        const uint32_t sB_ = sA_ + TILE_TK * HSTR * 2; \
        _Pragma("unroll") \
        for (int i = 0; i < 8; i++) \
            CP_ASYNC16(sA_ + (((arow + 32 * i) * HSTR + aq * 8) * 2), \
                       Ag + (size_t)(arow + 32 * i) * K + kofs_ + aq * 8); \
        _Pragma("unroll") \
        for (int i = 0; i < 4; i++) \
            CP_ASYNC16(sB_ + (((arow + 32 * i) * HSTR + aq * 8) * 2), \
                       Bg + (size_t)(arow + 32 * i) * K + kofs_ + aq * 8); \
    } while (0)

    // prologue: 3 chunks in flight
    ISSUE_CHUNK(0, 0); CP_COMMIT();
    ISSUE_CHUNK(1, 1); CP_COMMIT();
    ISSUE_CHUNK(2, 2); CP_COMMIT();

    for (int c = 0; c < chunks; c++) {
        CP_WAIT2();            // chunk c resident (at most 2 newer groups pending)
        __syncthreads();       // all warps done reading the slot we're about to overwrite

        if (c + STAGES - 1 < chunks) { ISSUE_CHUNK(c + STAGES - 1, (c + STAGES - 1) % STAGES); }
        CP_COMMIT();

        const uint32_t sA32 = sb32 + (c % STAGES) * STG_B;
        const uint32_t sB32 = sA32 + TILE_TK * HSTR * 2;

        #pragma unroll
        for (int ks = 0; ks < 4; ks++) {
            const int kb = ks * 16;
            uint32_t af[4][4];
            #pragma unroll
            for (int mt = 0; mt < 4; mt++) {
                const uint32_t addr = sA32 + (uint32_t)(((wm * 64 + mt * 16) * HSTR + kb) * 2) + a_lane;
                LDSM_X4(af[mt][0], af[mt][1], af[mt][2], af[mt][3], addr);
            }
            uint32_t bf[8][2];
            #pragma unroll
            for (int ntp = 0; ntp < 4; ntp++) {
                const uint32_t addr = sB32 + (uint32_t)(((wn * 64 + ntp * 16) * HSTR + kb) * 2) + b_lane;
                LDSM_X4(bf[2 * ntp][0], bf[2 * ntp][1], bf[2 * ntp + 1][0], bf[2 * ntp + 1][1], addr);
            }
            #pragma unroll
            for (int mt = 0; mt < 4; mt++)
                #pragma unroll
                for (int nt = 0; nt < 8; nt++)
                    mma16816(acc[mt][nt], af[mt], bf[nt]);
        }
    }
    #undef ISSUE_CHUNK

    float* C32 = reinterpret_cast<float*>(Cout);
    __half* C16 = reinterpret_cast<__half*>(Cout);

    #pragma unroll
    for (int mt = 0; mt < 4; mt++) {
        #pragma unroll
        for (int nt = 0; nt < 8; nt++) {
            const int col = n0 + wn * 64 + nt * 8 + 2 * t;
            float bx = 0.f, by = 0.f;
            if (BIAS) {
                const float2 b2 = *reinterpret_cast<const float2*>(bias + col);
                bx = b2.x; by = b2.y;
            }
            const int r1 = m0 + wm * 64 + mt * 16 + g;
            const int r2 = r1 + 8;

            float2 v1, v2;
            v1.x = acc[mt][nt][0] + bx; v1.y = acc[mt][nt][1] + by;
            v2.x = acc[mt][nt][2] + bx; v2.y = acc[mt][nt][3] + by;
            if (RELU) {
                v1.x = fmaxf(v1.x, 0.f); v1.y = fmaxf(v1.y, 0.f);
                v2.x = fmaxf(v2.x, 0.f); v2.y = fmaxf(v2.y, 0.f);
            }
            if (RES) {
                const float2 r1v = *reinterpret_cast<const float2*>(res + (size_t)r1 * Nout + col);
                const float2 r2v = *reinterpret_cast<const float2*>(res + (size_t)r2 * Nout + col);
                v1.x += r1v.x; v1.y += r1v.y;
                v2.x += r2v.x; v2.y += r2v.y;
            }
            if (OUT16) {
                *reinterpret_cast<uint32_t*>(C16 + (size_t)r1 * Nout + col) = packh2(v1.x, v1.y);
                *reinterpret_cast<uint32_t*>(C16 + (size_t)r2 * Nout + col) = packh2(v2.x, v2.y);
            } else {
                *reinterpret_cast<float2*>(C32 + (size_t)r1 * Nout + col) = v1;
                *reinterpret_cast<float2*>(C32 + (size_t)r2 * Nout + col) = v2;
            }
        }
    }
}

// ================= tensor-core causal attention (single-load, 5 syncs) =================
#define PSTR  136
#define AQSTR 264   // Q/K row stride (halves): 256 + 8 pad
#define SSTR  132   // S row stride (floats)
#define VSTR  130   // V^T row stride (halves): word-stride 65 == 1 mod 32
// bufA must hold BOTH phases: Q (128*AQSTR*2 = 67584 B) then V^T (256*VSTR*2 = 66560 B)
#define BUFA_B  (128 * AQSTR * 2)                  // 67584 (the max of the two)
#define OFF_BUFA (128 * PSTR * 2)                  // 34816
#define OFF_BUFB (OFF_BUFA + BUFA_B)               // 34816 + 67584 = 102400
#define ATTN_SMEM (OFF_BUFB + 128 * SSTR * 4)      // 102400 + 67584 = 169984

__global__ __launch_bounds__(256) void attention_k(
    const __half* __restrict__ qkv,   // [NTOK][4608]
    __half* __restrict__ o)           // [NTOK][1536]
{
    extern __shared__ char smem[];
    uint16_t* sP  = reinterpret_cast<uint16_t*>(smem);
    uint16_t* sQ  = reinterpret_cast<uint16_t*>(smem + OFF_BUFA);   // later V^T
    uint16_t* sVt = sQ;
    uint16_t* sK  = reinterpret_cast<uint16_t*>(smem + OFF_BUFB);   // later S (fp32)
    float*    sS  = reinterpret_cast<float*>(smem + OFF_BUFB);

    const int tid = threadIdx.x;
    const int wid = tid >> 5, lid = tid & 31;
    const int g = lid >> 2, t = lid & 3;
    const int wm = wid & 3;
    const int wn = wid >> 2;

    const int bh = blockIdx.x;
    const int b  = bh / HEADS;
    const int h  = bh - b * HEADS;

    const __half* qbase = qkv + (size_t)(b * SEQ) * QKVD + h * HEAD_DIM;
    const __half* kbase = qbase + CATD;
    const __half* vbase = qbase + 2 * CATD;
    __half* obase = o + (size_t)(b * SEQ) * CATD + h * HEAD_DIM;

    // ---- phase 1: load full Q, K (128 x 256 halves each) ----
    #pragma unroll
    for (int i = 0; i < 16; i++) {
        const int idx = tid + 256 * i;          // 4096 uint4 per tensor
        const int row = idx >> 5, q = idx & 31;
        *reinterpret_cast<uint4*>(sQ + row * AQSTR + q * 8) =
            *reinterpret_cast<const uint4*>(qbase + (size_t)row * QKVD + q * 8);
        *reinterpret_cast<uint4*>(sK + row * AQSTR + q * 8) =
            *reinterpret_cast<const uint4*>(kbase + (size_t)row * QKVD + q * 8);
    }
    __syncthreads();

    // ---- phase 2: S = Q K^T over full K=256, no intra-loop syncs ----
    float acc[2][8][4];
    #pragma unroll
    for (int i = 0; i < 2; i++)
        #pragma unroll
        for (int j = 0; j < 8; j++)
            #pragma unroll
            for (int r = 0; r < 4; r++) acc[i][j][r] = 0.f;

    #pragma unroll
    for (int ks = 0; ks < 16; ks++) {
        const int kb = ks * 16;
        uint32_t af[2][4];
        #pragma unroll
        for (int mt = 0; mt < 2; mt++) {
            const int rb = wm * 32 + mt * 16;
            af[mt][0] = *reinterpret_cast<const uint32_t*>(&sQ[(rb + g)     * AQSTR + kb + 2 * t]);
            af[mt][1] = *reinterpret_cast<const uint32_t*>(&sQ[(rb + g + 8) * AQSTR + kb + 2 * t]);
            af[mt][2] = *reinterpret_cast<const uint32_t*>(&sQ[(rb + g)     * AQSTR + kb + 2 * t + 8]);
            af[mt][3] = *reinterpret_cast<const uint32_t*>(&sQ[(rb + g + 8) * AQSTR + kb + 2 * t + 8]);
        }
        #pragma unroll
        for (int nt = 0; nt < 8; nt++) {
            if (wn * 64 + nt * 8 <= wm * 32 + 31) {   // causal tile skip
                const int cb = wn * 64 + nt * 8 + g;
                uint32_t bf[2];
                bf[0] = *reinterpret_cast<const uint32_t*>(&sK[cb * AQSTR + kb + 2 * t]);
                bf[1] = *reinterpret_cast<const uint32_t*>(&sK[cb * AQSTR + kb + 2 * t + 8]);
                #pragma unroll
                for (int mt = 0; mt < 2; mt++)
                    mma16816(acc[mt][nt], af[mt], bf);
            }
        }
    }
    __syncthreads();   // Q,K reads done; bufA/bufB reusable

    // ---- phase 3: write scaled S (bufB) + stage V^T (bufA) ----
    const float scale = 0.03608439182435161f; // 768^-0.5
    #pragma unroll
    for (int mt = 0; mt < 2; mt++) {
        #pragma unroll
        for (int nt = 0; nt < 8; nt++) {
            const int col = wn * 64 + nt * 8 + 2 * t;
            const int r1 = wm * 32 + mt * 16 + g;
            float2 v1, v2;
            v1.x = acc[mt][nt][0] * scale; v1.y = acc[mt][nt][1] * scale;
            v2.x = acc[mt][nt][2] * scale; v2.y = acc[mt][nt][3] * scale;
            *reinterpret_cast<float2*>(sS + (r1)     * SSTR + col) = v1;
            *reinterpret_cast<float2*>(sS + (r1 + 8) * SSTR + col) = v2;
        }
    }
    #pragma unroll
    for (int i = 0; i < 64; i++) {    // 16384 half2: s in 0..127, d2 in 0..127
        const int id = tid + 256 * i;
        const int s = id >> 7, d2 = id & 127;
        const uint32_t v2 = *reinterpret_cast<const uint32_t*>(
            vbase + (size_t)s * QKVD + 2 * d2);
        sVt[(2 * d2)     * VSTR + s] = (uint16_t)(v2 & 0xffffu);
        sVt[(2 * d2 + 1) * VSTR + s] = (uint16_t)(v2 >> 16);
    }
    __syncthreads();

    // ---- phase 4: softmax (one warp per row), P -> fp16 incl. zero fill ----
    for (int rr = wid; rr < 128; rr += 8) {
        const float* row = sS + rr * SSTR;
        float mx = -1e30f;
        #pragma unroll
        for (int i = 0; i < 4; i++) {
            const int s = lid + 32 * i;
            if (s <= rr) mx = fmaxf(mx, row[s]);
        }
        #pragma unroll
        for (int o2 = 16; o2; o2 >>= 1) mx = fmaxf(mx, __shfl_xor_sync(0xffffffffu, mx, o2));

        float e[4];
        float sum = 0.f;
        #pragma unroll
        for (int i = 0; i < 4; i++) {
            const int s = lid + 32 * i;
            e[i] = (s <= rr) ? __expf(row[s] - mx) : 0.f;
            sum += e[i];
        }
        #pragma unroll
        for (int o2 = 16; o2; o2 >>= 1) sum += __shfl_xor_sync(0xffffffffu, sum, o2);
        const float inv = 1.0f / sum;

        uint16_t* prow = sP + rr * PSTR;
        #pragma unroll
        for (int i = 0; i < 4; i++) {
            const int s = lid + 32 * i;
            const __half hv = __float2half_rn(e[i] * inv);
            prow[s] = *reinterpret_cast<const uint16_t*>(&hv);
        }
    }
    __syncthreads();

    // ---- phase 5: O = P V (4 d-chunks, no staging, no intra-loop syncs) ----
    #pragma unroll
    for (int c = 0; c < 4; c++) {
        float oacc[2][4][4];
        #pragma unroll
        for (int i = 0; i < 2; i++)
            #pragma unroll
            for (int j = 0; j < 4; j++)
                #pragma unroll
                for (int r = 0; r < 4; r++) oacc[i][j][r] = 0.f;

        #pragma unroll
        for (int ks = 0; ks < 8; ks++) {
            if (ks * 16 > wm * 32 + 31) break;   // causal: P cols beyond row range are zero
            const int kb = ks * 16;
            uint32_t af[2][4];
            #pragma unroll
            for (int mt = 0; mt < 2; mt++) {
                const int rb = wm * 32 + mt * 16;
                af[mt][0] = *reinterpret_cast<const uint32_t*>(&sP[(rb + g)     * PSTR + kb + 2 * t]);
                af[mt][1] = *reinterpret_cast<const uint32_t*>(&sP[(rb + g + 8) * PSTR + kb + 2 * t]);
                af[mt][2] = *reinterpret_cast<const uint32_t*>(&sP[(rb + g)     * PSTR + kb + 2 * t + 8]);
                af[mt][3] = *reinterpret_cast<const uint32_t*>(&sP[(rb + g + 8) * PSTR + kb + 2 * t + 8]);
            }
            #pragma unroll
            for (int nt = 0; nt < 4; nt++) {
                const int cb = c * 64 + wn * 32 + nt * 8 + g;
                uint32_t bf[2];
                bf[0] = *reinterpret_cast<const uint32_t*>(&sVt[cb * VSTR + kb + 2 * t]);
                bf[1] = *reinterpret_cast<const uint32_t*>(&sVt[cb * VSTR + kb + 2 * t + 8]);
                #pragma unroll
                for (int mt = 0; mt < 2; mt++)
                    mma16816(oacc[mt][nt], af[mt], bf);
            }
        }

        #pragma unroll
        for (int mt = 0; mt < 2; mt++) {
            #pragma unroll
            for (int nt = 0; nt < 4; nt++) {
                const int d = c * 64 + wn * 32 + nt * 8 + 2 * t;
                const int r1 = wm * 32 + mt * 16 + g;
                *reinterpret_cast<uint32_t*>(obase + (size_t)r1 * CATD + d) =
                    packh2(oacc[mt][nt][0], oacc[mt][nt][1]);
                *reinterpret_cast<uint32_t*>(obase + (size_t)(r1 + 8) * CATD + d) =
                    packh2(oacc[mt][nt][2], oacc[mt][nt][3]);
            }
        }
    }
}

// ================= launch =================
extern "C" void kernel_launch(void* const* d_in, const int* in_sizes, int n_in,
                              void* d_out, int out_size)
{
    const float* x   = (const float*)d_in[0];
    const float* Wq  = (const float*)d_in[1];
    const float* Wk  = (const float*)d_in[2];
    const float* Wv  = (const float*)d_in[3];
    const float* Wo  = (const float*)d_in[4];
    const float* bo  = (const float*)d_in[5];
    const float* W1  = (const float*)d_in[6];
    const float* b1  = (const float*)d_in[7];
    const float* W2  = (const float*)d_in[8];
    const float* b2  = (const float*)d_in[9];
    const float* g1  = (const float*)d_in[10];
    const float* be1 = (const float*)d_in[11];
    const float* g2  = (const float*)d_in[12];
    const float* be2 = (const float*)d_in[13];
    float* out = (float*)d_out;

    void *phh, *pqkv, *poh, *pres, *pmid, *pwqkv, *pwto, *pwt1, *pwt2;
    cudaGetSymbolAddress(&phh,  g_hh);
    cudaGetSymbolAddress(&pqkv, g_qkv);
    cudaGetSymbolAddress(&poh,  g_oh);
    cudaGetSymbolAddress(&pres, g_res);
    cudaGetSymbolAddress(&pmid, g_mid);
    cudaGetSymbolAddress(&pwqkv, g_wqkv);
    cudaGetSymbolAddress(&pwto, g_wto);
    cudaGetSymbolAddress(&pwt1, g_wt1);
    cudaGetSymbolAddress(&pwt2, g_wt2);
    __half* H    = (__half*)phh;
    __half* QKV  = (__half*)pqkv;
    __half* O    = (__half*)poh;
    float*  R    = (float*)pres;
    __half* MID  = (__half*)pmid;
    __half* WQKV = (__half*)pwqkv;
    __half* WTO  = (__half*)pwto;
    __half* WT1  = (__half*)pwt1;
    __half* WT2  = (__half*)pwt2;

    cudaFuncSetAttribute(attention_k, cudaFuncAttributeMaxDynamicSharedMemorySize, ATTN_SMEM);
    cudaFuncSetAttribute(gemm_tc<true,  false, false, false>, cudaFuncAttributeMaxDynamicSharedMemorySize, GEMM_SMEM);
    cudaFuncSetAttribute(gemm_tc<false, true,  false, true >, cudaFuncAttributeMaxDynamicSharedMemorySize, GEMM_SMEM);
    cudaFuncSetAttribute(gemm_tc<true,  true,  true,  false>, cudaFuncAttributeMaxDynamicSharedMemorySize, GEMM_SMEM);

    dim3 tt(32, 8);
    transpose_k<<<dim3(CATD / 32, EMBED / 32), tt>>>(Wq, WQKV,                        EMBED, CATD, HEAD_DIM);
    transpose_k<<<dim3(CATD / 32, EMBED / 32), tt>>>(Wk, WQKV + (size_t)CATD * EMBED, EMBED, CATD, HEAD_DIM);
    transpose_k<<<dim3(CATD / 32, EMBED / 32), tt>>>(Wv, WQKV + (size_t)2 * CATD * EMBED, EMBED, CATD, HEAD_DIM);
    transpose_k<<<dim3(EMBED / 32, CATD / 32), tt>>>(Wo, WTO, CATD, EMBED, EMBED);
    transpose_k<<<dim3(FFN / 32, EMBED / 32),  tt>>>(W1, WT1, EMBED, FFN, FFN);
    transpose_k<<<dim3(EMBED / 32, FFN / 32),  tt>>>(W2, WT2, FFN, EMBED, EMBED);

    layernorm_k<<<NTOK, 256>>>(x, H, g1, be1);

    gemm_tc<true, false, false, false><<<dim3(QKVD / TILE_NF, NTOK / TILE_TK), 256, GEMM_SMEM>>>(
        WQKV, H, QKV, EMBED, QKVD, nullptr, nullptr);

    attention_k<<<BATCH * HEADS, 256, ATTN_SMEM>>>(QKV, O);

    gemm_tc<false, true, false, true><<<dim3(EMBED / TILE_NF, NTOK / TILE_TK), 256, GEMM_SMEM>>>(
        WTO, O, R, CATD, EMBED, bo, x);

    layernorm_k<<<NTOK, 256>>>(R, H, g2, be2);

    gemm_tc<true, true, true, false><<<dim3(FFN / TILE_NF, NTOK / TILE_TK), 256, GEMM_SMEM>>>(
        WT1, H, MID, EMBED, FFN, b1, nullptr);

    gemm_tc<false, true, false, true><<<dim3(EMBED / TILE_NF, NTOK / TILE_TK), 256, GEMM_SMEM>>>(
        WT2, MID, out, FFN, EMBED, b2, R);
}

// round 13
// speedup vs baseline: 1.0093x; 1.0093x over previous
#include <cuda_runtime.h>
#include <cuda_fp16.h>
#include <cstdint>

#define EMBED    768
#define HEADS    6
#define HEAD_DIM 256
#define SEQ      128
#define BATCH    512
#define NTOK     (BATCH * SEQ)        // 65536
#define CATD     (HEADS * HEAD_DIM)   // 1536
#define QKVD     (3 * CATD)           // 4608
#define FFN      (4 * EMBED)          // 3072

// ================= helpers =================
__device__ __forceinline__ uint32_t packh2(float lo, float hi) {
    uint32_t r;
    asm("cvt.rn.f16x2.f32 %0, %1, %2;" : "=r"(r) : "f"(hi), "f"(lo));
    return r;
}
__device__ __forceinline__ void mma16816(float* c, const uint32_t* a, const uint32_t* b) {
    asm volatile(
        "mma.sync.aligned.m16n8k16.row.col.f32.f16.f16.f32 "
        "{%0,%1,%2,%3}, {%4,%5,%6,%7}, {%8,%9}, {%0,%1,%2,%3};"
        : "+f"(c[0]), "+f"(c[1]), "+f"(c[2]), "+f"(c[3])
        : "r"(a[0]), "r"(a[1]), "r"(a[2]), "r"(a[3]), "r"(b[0]), "r"(b[1]));
}
__device__ __forceinline__ uint32_t smem_u32(const void* p) {
    uint32_t a;
    asm("{ .reg .u64 t; cvta.to.shared.u64 t, %1; cvt.u32.u64 %0, t; }" : "=r"(a) : "l"(p));
    return a;
}
#define CP_ASYNC16(saddr, gptr) \
    asm volatile("cp.async.cg.shared.global [%0], [%1], 16;" :: "r"(saddr), "l"(gptr))
#define CP_COMMIT() asm volatile("cp.async.commit_group;" ::: "memory")
#define CP_WAIT1()  asm volatile("cp.async.wait_group 1;" ::: "memory")
#define LDSM_X4(r0, r1, r2, r3, addr) \
    asm volatile("ldmatrix.sync.aligned.m8n8.x4.shared.b16 {%0,%1,%2,%3}, [%4];" \
        : "=r"(r0), "=r"(r1), "=r"(r2), "=r"(r3) : "r"(addr))

// GEMM tiling (R9-proven config: 3 stages, wait_group 1)
#define TILE_NF  128
#define TILE_TK  256
#define KCH      64
#define HSTR     72                                    // halves per smem row (64 + 8 pad)
#define STAGES   3
#define STG_H    ((TILE_TK + TILE_NF) * HSTR)          // halves per stage
#define STG_B    (STG_H * 2)                           // bytes per stage (55296)
#define GEMM_SMEM (STAGES * STG_B)                     // 165888 B

// residual modes
#define RES_NONE 0
#define RES_F32  1
#define RES_F16  2

// ================= scratch =================
__device__ __half g_hh  [(size_t)NTOK * EMBED];
__device__ __half g_qkv [(size_t)NTOK * QKVD];
__device__ __half g_oh  [(size_t)NTOK * CATD];
__device__ __half g_res [(size_t)NTOK * EMBED];   // attn_out residual, fp16
__device__ __half g_mid [(size_t)NTOK * FFN];
__device__ __half g_wqkv[(size_t)QKVD * EMBED];
__device__ __half g_wto [(size_t)EMBED * CATD];
__device__ __half g_wt1 [(size_t)FFN * EMBED];
__device__ __half g_wt2 [(size_t)EMBED * FFN];

// ================= transpose: in(k, n) -> out[n][k] (fp16 out) =================
__global__ __launch_bounds__(256) void transpose_k(
    const float* __restrict__ in, __half* __restrict__ out, int Kdim, int N, int Dh)
{
    __shared__ float t[32][33];
    const int k0 = blockIdx.y * 32;
    const int n0 = blockIdx.x * 32;
    const int tx = threadIdx.x, ty = threadIdx.y;

    #pragma unroll
    for (int i = 0; i < 4; i++) {
        const int k = k0 + ty + 8 * i;
        const int n = n0 + tx;
        const int h = n / Dh, d = n - h * Dh;
        t[ty + 8 * i][tx] = in[(size_t)h * Kdim * Dh + (size_t)k * Dh + d];
    }
    __syncthreads();
    #pragma unroll
    for (int i = 0; i < 4; i++) {
        out[(size_t)(n0 + ty + 8 * i) * Kdim + k0 + tx] = __float2half_rn(t[tx][ty + 8 * i]);
    }
}

// ================= LayerNorm (fp32 or fp16 in -> fp16 out) =================
template<typename Tin>
__global__ __launch_bounds__(256) void layernorm_k(
    const Tin* __restrict__ x, __half* __restrict__ y,
    const float* __restrict__ g, const float* __restrict__ b)
{
    const int row = blockIdx.x;
    const int tid = threadIdx.x;
    const Tin* xr = x + (size_t)row * EMBED;

    float v0 = (float)xr[tid];
    float v1 = (float)xr[tid + 256];
    float v2 = (float)xr[tid + 512];

    float s = v0 + v1 + v2;
    float q = v0 * v0 + v1 * v1 + v2 * v2;

    #pragma unroll
    for (int o = 16; o; o >>= 1) {
        s += __shfl_xor_sync(0xffffffffu, s, o);
        q += __shfl_xor_sync(0xffffffffu, q, o);
    }
    __shared__ float ss[8], sq[8];
    const int w = tid >> 5, l = tid & 31;
    if (l == 0) { ss[w] = s; sq[w] = q; }
    __syncthreads();
    float S = 0.f, Q = 0.f;
    #pragma unroll
    for (int i = 0; i < 8; i++) { S += ss[i]; Q += sq[i]; }

    const float mu  = S * (1.0f / EMBED);
    const float var = Q * (1.0f / EMBED) - mu * mu;
    const float inv = rsqrtf(var + 1e-5f);

    __half* yr = y + (size_t)row * EMBED;
    yr[tid]       = __float2half_rn((v0 - mu) * inv * g[tid]       + b[tid]);
    yr[tid + 256] = __float2half_rn((v1 - mu) * inv * g[tid + 256] + b[tid + 256]);
    yr[tid + 512] = __float2half_rn((v2 - mu) * inv * g[tid + 512] + b[tid + 512]);
}

// ================= GEMM (fp16, 3-stage cp.async, ldmatrix) =================
// C[m,n] = sum_k Hm[m,k]*Wt[n,k] (+bias)(relu)(+res)
template<bool OUT16, bool BIAS, bool RELU, int RESM>
__global__ __launch_bounds__(256) void gemm_tc(
    const __half* __restrict__ Wt,   // [Nout, K]  K-major fp16
    const __half* __restrict__ Hm,   // [NTOK, K]  fp16
    void* __restrict__ Cout,         // fp16 or fp32 [NTOK, Nout]
    int K, int Nout,
    const float* __restrict__ bias,
    const void* __restrict__ res)    // fp32 or fp16 per RESM
{
    extern __shared__ char smem[];
    const uint32_t sb32 = smem_u32(smem);

    const int tid = threadIdx.x;
    const int wid = tid >> 5, lid = tid & 31;
    const int g = lid >> 2, t = lid & 3;
    const int wm = wid & 3;
    const int wn = wid >> 2;

    const int n0 = blockIdx.x * TILE_NF;
    const int m0 = blockIdx.y * TILE_TK;
    const int chunks = K / KCH;

    const __half* Ag = Hm + (size_t)m0 * K;
    const __half* Bg = Wt + (size_t)n0 * K;

    const int arow = tid >> 3, aq = tid & 7;

    const uint32_t a_lane = (uint32_t)(((lid & 15) * HSTR + ((lid >> 4) << 3)) * 2);
    const uint32_t b_lane = (uint32_t)((((lid & 7) + ((lid >> 4) << 3)) * HSTR + ((lid >> 3) & 1) * 8) * 2);

    float acc[4][8][4];
    #pragma unroll
    for (int i = 0; i < 4; i++)
        #pragma unroll
        for (int j = 0; j < 8; j++)
            #pragma unroll
            for (int r = 0; r < 4; r++) acc[i][j][r] = 0.f;

    #define ISSUE_CHUNK(chunk, stg) do { \
        const int kofs_ = (chunk) * KCH; \
        const uint32_t sA_ = sb32 + (stg) * STG_B; \
        const uint32_t sB_ = sA_ + TILE_TK * HSTR * 2; \
        _Pragma("unroll") \
        for (int i = 0; i < 8; i++) \
            CP_ASYNC16(sA_ + (((arow + 32 * i) * HSTR + aq * 8) * 2), \
                       Ag + (size_t)(arow + 32 * i) * K + kofs_ + aq * 8); \
        _Pragma("unroll") \
        for (int i = 0; i < 4; i++) \
            CP_ASYNC16(sB_ + (((arow + 32 * i) * HSTR + aq * 8) * 2), \
                       Bg + (size_t)(arow + 32 * i) * K + kofs_ + aq * 8); \
    } while (0)

    ISSUE_CHUNK(0, 0); CP_COMMIT();
    if (chunks > 1) { ISSUE_CHUNK(1, 1); } CP_COMMIT();

    for (int c = 0; c < chunks; c++) {
        CP_WAIT1();
        __syncthreads();

        if (c + STAGES - 1 < chunks) { ISSUE_CHUNK(c + STAGES - 1, (c + STAGES - 1) % STAGES); }
        CP_COMMIT();

        const uint32_t sA32 = sb32 + (c % STAGES) * STG_B;
        const uint32_t sB32 = sA32 + TILE_TK * HSTR * 2;

        #pragma unroll
        for (int ks = 0; ks < 4; ks++) {
            const int kb = ks * 16;
            uint32_t af[4][4];
            #pragma unroll
            for (int mt = 0; mt < 4; mt++) {
                const uint32_t addr = sA32 + (uint32_t)(((wm * 64 + mt * 16) * HSTR + kb) * 2) + a_lane;
                LDSM_X4(af[mt][0], af[mt][1], af[mt][2], af[mt][3], addr);
            }
            uint32_t bf[8][2];
            #pragma unroll
            for (int ntp = 0; ntp < 4; ntp++) {
                const uint32_t addr = sB32 + (uint32_t)(((wn * 64 + ntp * 16) * HSTR + kb) * 2) + b_lane;
                LDSM_X4(bf[2 * ntp][0], bf[2 * ntp][1], bf[2 * ntp + 1][0], bf[2 * ntp + 1][1], addr);
            }
            #pragma unroll
            for (int mt = 0; mt < 4; mt++)
                #pragma unroll
                for (int nt = 0; nt < 8; nt++)
                    mma16816(acc[mt][nt], af[mt], bf[nt]);
        }
    }
    #undef ISSUE_CHUNK

    float* C32 = reinterpret_cast<float*>(Cout);
    __half* C16 = reinterpret_cast<__half*>(Cout);
    const float* R32 = reinterpret_cast<const float*>(res);
    const __half* R16 = reinterpret_cast<const __half*>(res);

    #pragma unroll
    for (int mt = 0; mt < 4; mt++) {
        #pragma unroll
        for (int nt = 0; nt < 8; nt++) {
            const int col = n0 + wn * 64 + nt * 8 + 2 * t;
            float bx = 0.f, by = 0.f;
            if (BIAS) {
                const float2 b2 = *reinterpret_cast<const float2*>(bias + col);
                bx = b2.x; by = b2.y;
            }
            const int r1 = m0 + wm * 64 + mt * 16 + g;
            const int r2 = r1 + 8;

            float2 v1, v2;
            v1.x = acc[mt][nt][0] + bx; v1.y = acc[mt][nt][1] + by;
            v2.x = acc[mt][nt][2] + bx; v2.y = acc[mt][nt][3] + by;
            if (RELU) {
                v1.x = fmaxf(v1.x, 0.f); v1.y = fmaxf(v1.y, 0.f);
                v2.x = fmaxf(v2.x, 0.f); v2.y = fmaxf(v2.y, 0.f);
            }
            if (RESM == RES_F32) {
                const float2 r1v = *reinterpret_cast<const float2*>(R32 + (size_t)r1 * Nout + col);
                const float2 r2v = *reinterpret_cast<const float2*>(R32 + (size_t)r2 * Nout + col);
                v1.x += r1v.x; v1.y += r1v.y;
                v2.x += r2v.x; v2.y += r2v.y;
            } else if (RESM == RES_F16) {
                const __half2 r1h = *reinterpret_cast<const __half2*>(R16 + (size_t)r1 * Nout + col);
                const __half2 r2h = *reinterpret_cast<const __half2*>(R16 + (size_t)r2 * Nout + col);
                const float2 r1v = __half22float2(r1h);
                const float2 r2v = __half22float2(r2h);
                v1.x += r1v.x; v1.y += r1v.y;
                v2.x += r2v.x; v2.y += r2v.y;
            }
            if (OUT16) {
                *reinterpret_cast<uint32_t*>(C16 + (size_t)r1 * Nout + col) = packh2(v1.x, v1.y);
                *reinterpret_cast<uint32_t*>(C16 + (size_t)r2 * Nout + col) = packh2(v2.x, v2.y);
            } else {
                *reinterpret_cast<float2*>(C32 + (size_t)r1 * Nout + col) = v1;
                *reinterpret_cast<float2*>(C32 + (size_t)r2 * Nout + col) = v2;
            }
        }
    }
}

// ================= tensor-core causal attention (single-load, 5 syncs) =================
#define PSTR  136
#define AQSTR 264   // Q/K row stride (halves): 256 + 8 pad
#define SSTR  132   // S row stride (floats)
#define VSTR  130   // V^T row stride (halves)
// bufA must hold BOTH phases: Q (128*AQSTR*2 = 67584 B) then V^T (256*VSTR*2 = 66560 B)
#define BUFA_B  (128 * AQSTR * 2)                  // 67584
#define OFF_BUFA (128 * PSTR * 2)                  // 34816
#define OFF_BUFB (OFF_BUFA + BUFA_B)               // 102400
#define ATTN_SMEM (OFF_BUFB + 128 * SSTR * 4)      // 169984

__global__ __launch_bounds__(256) void attention_k(
    const __half* __restrict__ qkv,   // [NTOK][4608]
    __half* __restrict__ o)           // [NTOK][1536]
{
    extern __shared__ char smem[];
    uint16_t* sP  = reinterpret_cast<uint16_t*>(smem);
    uint16_t* sQ  = reinterpret_cast<uint16_t*>(smem + OFF_BUFA);   // later V^T
    uint16_t* sVt = sQ;
    uint16_t* sK  = reinterpret_cast<uint16_t*>(smem + OFF_BUFB);   // later S (fp32)
    float*    sS  = reinterpret_cast<float*>(smem + OFF_BUFB);

    const int tid = threadIdx.x;
    const int wid = tid >> 5, lid = tid & 31;
    const int g = lid >> 2, t = lid & 3;
    const int wm = wid & 3;
    const int wn = wid >> 2;

    const int bh = blockIdx.x;
    const int b  = bh / HEADS;
    const int h  = bh - b * HEADS;

    const __half* qbase = qkv + (size_t)(b * SEQ) * QKVD + h * HEAD_DIM;
    const __half* kbase = qbase + CATD;
    const __half* vbase = qbase + 2 * CATD;
    __half* obase = o + (size_t)(b * SEQ) * CATD + h * HEAD_DIM;

    // ---- phase 1: load full Q, K ----
    #pragma unroll
    for (int i = 0; i < 16; i++) {
        const int idx = tid + 256 * i;
        const int row = idx >> 5, q = idx & 31;
        *reinterpret_cast<uint4*>(sQ + row * AQSTR + q * 8) =
            *reinterpret_cast<const uint4*>(qbase + (size_t)row * QKVD + q * 8);
        *reinterpret_cast<uint4*>(sK + row * AQSTR + q * 8) =
            *reinterpret_cast<const uint4*>(kbase + (size_t)row * QKVD + q * 8);
    }
    __syncthreads();

    // ---- phase 2: S = Q K^T ----
    float acc[2][8][4];
    #pragma unroll
    for (int i = 0; i < 2; i++)
        #pragma unroll
        for (int j = 0; j < 8; j++)
            #pragma unroll
            for (int r = 0; r < 4; r++) acc[i][j][r] = 0.f;

    #pragma unroll
    for (int ks = 0; ks < 16; ks++) {
        const int kb = ks * 16;
        uint32_t af[2][4];
        #pragma unroll
        for (int mt = 0; mt < 2; mt++) {
            const int rb = wm * 32 + mt * 16;
            af[mt][0] = *reinterpret_cast<const uint32_t*>(&sQ[(rb + g)     * AQSTR + kb + 2 * t]);
            af[mt][1] = *reinterpret_cast<const uint32_t*>(&sQ[(rb + g + 8) * AQSTR + kb + 2 * t]);
            af[mt][2] = *reinterpret_cast<const uint32_t*>(&sQ[(rb + g)     * AQSTR + kb + 2 * t + 8]);
            af[mt][3] = *reinterpret_cast<const uint32_t*>(&sQ[(rb + g + 8) * AQSTR + kb + 2 * t + 8]);
        }
        #pragma unroll
        for (int nt = 0; nt < 8; nt++) {
            if (wn * 64 + nt * 8 <= wm * 32 + 31) {
                const int cb = wn * 64 + nt * 8 + g;
                uint32_t bf[2];
                bf[0] = *reinterpret_cast<const uint32_t*>(&sK[cb * AQSTR + kb + 2 * t]);
                bf[1] = *reinterpret_cast<const uint32_t*>(&sK[cb * AQSTR + kb + 2 * t + 8]);
                #pragma unroll
                for (int mt = 0; mt < 2; mt++)
                    mma16816(acc[mt][nt], af[mt], bf);
            }
        }
    }
    __syncthreads();

    // ---- phase 3: write scaled S + stage V^T ----
    const float scale = 0.03608439182435161f; // 768^-0.5
    #pragma unroll
    for (int mt = 0; mt < 2; mt++) {
        #pragma unroll
        for (int nt = 0; nt < 8; nt++) {
            const int col = wn * 64 + nt * 8 + 2 * t;
            const int r1 = wm * 32 + mt * 16 + g;
            float2 v1, v2;
            v1.x = acc[mt][nt][0] * scale; v1.y = acc[mt][nt][1] * scale;
            v2.x = acc[mt][nt][2] * scale; v2.y = acc[mt][nt][3] * scale;
            *reinterpret_cast<float2*>(sS + (r1)     * SSTR + col) = v1;
            *reinterpret_cast<float2*>(sS + (r1 + 8) * SSTR + col) = v2;
        }
    }
    #pragma unroll
    for (int i = 0; i < 64; i++) {
        const int id = tid + 256 * i;
        const int s = id >> 7, d2 = id & 127;
        const uint32_t v2 = *reinterpret_cast<const uint32_t*>(
            vbase + (size_t)s * QKVD + 2 * d2);
        sVt[(2 * d2)     * VSTR + s] = (uint16_t)(v2 & 0xffffu);
        sVt[(2 * d2 + 1) * VSTR + s] = (uint16_t)(v2 >> 16);
    }
    __syncthreads();

    // ---- phase 4: softmax (one warp per row) ----
    for (int rr = wid; rr < 128; rr += 8) {
        const float* row = sS + rr * SSTR;
        float mx = -1e30f;
        #pragma unroll
        for (int i = 0; i < 4; i++) {
            const int s = lid + 32 * i;
            if (s <= rr) mx = fmaxf(mx, row[s]);
        }
        #pragma unroll
        for (int o2 = 16; o2; o2 >>= 1) mx = fmaxf(mx, __shfl_xor_sync(0xffffffffu, mx, o2));

        float e[4];
        float sum = 0.f;
        #pragma unroll
        for (int i = 0; i < 4; i++) {
            const int s = lid + 32 * i;
            e[i] = (s <= rr) ? __expf(row[s] - mx) : 0.f;
            sum += e[i];
        }
        #pragma unroll
        for (int o2 = 16; o2; o2 >>= 1) sum += __shfl_xor_sync(0xffffffffu, sum, o2);
        const float inv = 1.0f / sum;

        uint16_t* prow = sP + rr * PSTR;
        #pragma unroll
        for (int i = 0; i < 4; i++) {
            const int s = lid + 32 * i;
            const __half hv = __float2half_rn(e[i] * inv);
            prow[s] = *reinterpret_cast<const uint16_t*>(&hv);
        }
    }
    __syncthreads();

    // ---- phase 5: O = P V ----
    #pragma unroll
    for (int c = 0; c < 4; c++) {
        float oacc[2][4][4];
        #pragma unroll
        for (int i = 0; i < 2; i++)
            #pragma unroll
            for (int j = 0; j < 4; j++)
                #pragma unroll
                for (int r = 0; r < 4; r++) oacc[i][j][r] = 0.f;

        #pragma unroll
        for (int ks = 0; ks < 8; ks++) {
            if (ks * 16 > wm * 32 + 31) break;
            const int kb = ks * 16;
            uint32_t af[2][4];
            #pragma unroll
            for (int mt = 0; mt < 2; mt++) {
                const int rb = wm * 32 + mt * 16;
                af[mt][0] = *reinterpret_cast<const uint32_t*>(&sP[(rb + g)     * PSTR + kb + 2 * t]);
                af[mt][1] = *reinterpret_cast<const uint32_t*>(&sP[(rb + g + 8) * PSTR + kb + 2 * t]);
                af[mt][2] = *reinterpret_cast<const uint32_t*>(&sP[(rb + g)     * PSTR + kb + 2 * t + 8]);
                af[mt][3] = *reinterpret_cast<const uint32_t*>(&sP[(rb + g + 8) * PSTR + kb + 2 * t + 8]);
            }
            #pragma unroll
            for (int nt = 0; nt < 4; nt++) {
                const int cb = c * 64 + wn * 32 + nt * 8 + g;
                uint32_t bf[2];
                bf[0] = *reinterpret_cast<const uint32_t*>(&sVt[cb * VSTR + kb + 2 * t]);
                bf[1] = *reinterpret_cast<const uint32_t*>(&sVt[cb * VSTR + kb + 2 * t + 8]);
                #pragma unroll
                for (int mt = 0; mt < 2; mt++)
                    mma16816(oacc[mt][nt], af[mt], bf);
            }
        }

        #pragma unroll
        for (int mt = 0; mt < 2; mt++) {
            #pragma unroll
            for (int nt = 0; nt < 4; nt++) {
                const int d = c * 64 + wn * 32 + nt * 8 + 2 * t;
                const int r1 = wm * 32 + mt * 16 + g;
                *reinterpret_cast<uint32_t*>(obase + (size_t)r1 * CATD + d) =
                    packh2(oacc[mt][nt][0], oacc[mt][nt][1]);
                *reinterpret_cast<uint32_t*>(obase + (size_t)(r1 + 8) * CATD + d) =
                    packh2(oacc[mt][nt][2], oacc[mt][nt][3]);
            }
        }
    }
}

// ================= launch =================
extern "C" void kernel_launch(void* const* d_in, const int* in_sizes, int n_in,
                              void* d_out, int out_size)
{
    const float* x   = (const float*)d_in[0];
    const float* Wq  = (const float*)d_in[1];
    const float* Wk  = (const float*)d_in[2];
    const float* Wv  = (const float*)d_in[3];
    const float* Wo  = (const float*)d_in[4];
    const float* bo  = (const float*)d_in[5];
    const float* W1  = (const float*)d_in[6];
    const float* b1  = (const float*)d_in[7];
    const float* W2  = (const float*)d_in[8];
    const float* b2  = (const float*)d_in[9];
    const float* g1  = (const float*)d_in[10];
    const float* be1 = (const float*)d_in[11];
    const float* g2  = (const float*)d_in[12];
    const float* be2 = (const float*)d_in[13];
    float* out = (float*)d_out;

    void *phh, *pqkv, *poh, *pres, *pmid, *pwqkv, *pwto, *pwt1, *pwt2;
    cudaGetSymbolAddress(&phh,  g_hh);
    cudaGetSymbolAddress(&pqkv, g_qkv);
    cudaGetSymbolAddress(&poh,  g_oh);
    cudaGetSymbolAddress(&pres, g_res);
    cudaGetSymbolAddress(&pmid, g_mid);
    cudaGetSymbolAddress(&pwqkv, g_wqkv);
    cudaGetSymbolAddress(&pwto, g_wto);
    cudaGetSymbolAddress(&pwt1, g_wt1);
    cudaGetSymbolAddress(&pwt2, g_wt2);
    __half* H    = (__half*)phh;
    __half* QKV  = (__half*)pqkv;
    __half* O    = (__half*)poh;
    __half* R    = (__half*)pres;
    __half* MID  = (__half*)pmid;
    __half* WQKV = (__half*)pwqkv;
    __half* WTO  = (__half*)pwto;
    __half* WT1  = (__half*)pwt1;
    __half* WT2  = (__half*)pwt2;

    cudaFuncSetAttribute(attention_k, cudaFuncAttributeMaxDynamicSharedMemorySize, ATTN_SMEM);
    cudaFuncSetAttribute(gemm_tc<true,  false, false, RES_NONE>, cudaFuncAttributeMaxDynamicSharedMemorySize, GEMM_SMEM);
    cudaFuncSetAttribute(gemm_tc<true,  true,  false, RES_F32 >, cudaFuncAttributeMaxDynamicSharedMemorySize, GEMM_SMEM);
    cudaFuncSetAttribute(gemm_tc<true,  true,  true,  RES_NONE>, cudaFuncAttributeMaxDynamicSharedMemorySize, GEMM_SMEM);
    cudaFuncSetAttribute(gemm_tc<false, true,  false, RES_F16 >, cudaFuncAttributeMaxDynamicSharedMemorySize, GEMM_SMEM);

    dim3 tt(32, 8);
    transpose_k<<<dim3(CATD / 32, EMBED / 32), tt>>>(Wq, WQKV,                        EMBED, CATD, HEAD_DIM);
    transpose_k<<<dim3(CATD / 32, EMBED / 32), tt>>>(Wk, WQKV + (size_t)CATD * EMBED, EMBED, CATD, HEAD_DIM);
    transpose_k<<<dim3(CATD / 32, EMBED / 32), tt>>>(Wv, WQKV + (size_t)2 * CATD * EMBED, EMBED, CATD, HEAD_DIM);
    transpose_k<<<dim3(EMBED / 32, CATD / 32), tt>>>(Wo, WTO, CATD, EMBED, EMBED);
    transpose_k<<<dim3(FFN / 32, EMBED / 32),  tt>>>(W1, WT1, EMBED, FFN, FFN);
    transpose_k<<<dim3(EMBED / 32, FFN / 32),  tt>>>(W2, WT2, FFN, EMBED, EMBED);

    // LN1 (fp32 in)
    layernorm_k<float><<<NTOK, 256>>>(x, H, g1, be1);

    // fused QKV projection -> fp16
    gemm_tc<true, false, false, RES_NONE><<<dim3(QKVD / TILE_NF, NTOK / TILE_TK), 256, GEMM_SMEM>>>(
        WQKV, H, QKV, EMBED, QKVD, nullptr, nullptr);

    // attention
    attention_k<<<BATCH * HEADS, 256, ATTN_SMEM>>>(QKV, O);

    // attn_out = O @ Wo + bo + x  -> fp16 R
    gemm_tc<true, true, false, RES_F32><<<dim3(EMBED / TILE_NF, NTOK / TILE_TK), 256, GEMM_SMEM>>>(
        WTO, O, R, CATD, EMBED, bo, x);

    // LN2 (fp16 in)
    layernorm_k<__half><<<NTOK, 256>>>(R, H, g2, be2);

    // MID = relu(H @ W1 + b1)  (fp16)
    gemm_tc<true, true, true, RES_NONE><<<dim3(FFN / TILE_NF, NTOK / TILE_TK), 256, GEMM_SMEM>>>(
        WT1, H, MID, EMBED, FFN, b1, nullptr);

    // out = MID @ W2 + b2 + R  (fp32 out, fp16 residual)
    gemm_tc<false, true, false, RES_F16><<<dim3(EMBED / TILE_NF, NTOK / TILE_TK), 256, GEMM_SMEM>>>(
        WT2, MID, out, FFN, EMBED, b2, R);
}

// round 15
// speedup vs baseline: 1.0102x; 1.0009x over previous
#include <cuda_runtime.h>
#include <cuda_fp16.h>
#include <cstdint>

#define EMBED    768
#define HEADS    6
#define HEAD_DIM 256
#define SEQ      128
#define BATCH    512
#define NTOK     (BATCH * SEQ)        // 65536
#define CATD     (HEADS * HEAD_DIM)   // 1536
#define QKVD     (3 * CATD)           // 4608
#define FFN      (4 * EMBED)          // 3072

// ================= helpers =================
__device__ __forceinline__ uint32_t packh2(float lo, float hi) {
    uint32_t r;
    asm("cvt.rn.f16x2.f32 %0, %1, %2;" : "=r"(r) : "f"(hi), "f"(lo));
    return r;
}
__device__ __forceinline__ void mma16816(float* c, const uint32_t* a, const uint32_t* b) {
    asm volatile(
        "mma.sync.aligned.m16n8k16.row.col.f32.f16.f16.f32 "
        "{%0,%1,%2,%3}, {%4,%5,%6,%7}, {%8,%9}, {%0,%1,%2,%3};"
        : "+f"(c[0]), "+f"(c[1]), "+f"(c[2]), "+f"(c[3])
        : "r"(a[0]), "r"(a[1]), "r"(a[2]), "r"(a[3]), "r"(b[0]), "r"(b[1]));
}
__device__ __forceinline__ uint32_t smem_u32(const void* p) {
    uint32_t a;
    asm("{ .reg .u64 t; cvta.to.shared.u64 t, %1; cvt.u32.u64 %0, t; }" : "=r"(a) : "l"(p));
    return a;
}
#define CP_ASYNC16(saddr, gptr) \
    asm volatile("cp.async.cg.shared.global [%0], [%1], 16;" :: "r"(saddr), "l"(gptr))
#define CP_COMMIT() asm volatile("cp.async.commit_group;" ::: "memory")
#define CP_WAIT1()  asm volatile("cp.async.wait_group 1;" ::: "memory")
#define LDSM_X4(r0, r1, r2, r3, addr) \
    asm volatile("ldmatrix.sync.aligned.m8n8.x4.shared.b16 {%0,%1,%2,%3}, [%4];" \
        : "=r"(r0), "=r"(r1), "=r"(r2), "=r"(r3) : "r"(addr))

// GEMM tiling (R9/R10-proven config: 3 stages, wait_group 1, KCH=64, ldmatrix)
#define TILE_NF  128
#define TILE_TK  256
#define KCH      64
#define HSTR     72
#define STAGES   3
#define STG_H    ((TILE_TK + TILE_NF) * HSTR)
#define STG_B    (STG_H * 2)                           // 55296
#define GEMM_SMEM (STAGES * STG_B)                     // 165888

// ================= scratch =================
__device__ __half g_hh  [(size_t)NTOK * EMBED];
__device__ __half g_qkv [(size_t)NTOK * QKVD];
__device__ __half g_oh  [(size_t)NTOK * CATD];
__device__ float  g_res [(size_t)NTOK * EMBED];   // attn_out residual (fp32 — proven best)
__device__ __half g_mid [(size_t)NTOK * FFN];
__device__ __half g_wqkv[(size_t)QKVD * EMBED];
__device__ __half g_wto [(size_t)EMBED * CATD];
__device__ __half g_wt1 [(size_t)FFN * EMBED];
__device__ __half g_wt2 [(size_t)EMBED * FFN];

// ================= fused transpose: all 6 weights in ONE launch (9216 blocks) =================
// out[n][k] = in(k, n), with per-head addressing addr(k,n) = (n/Dh)*Kdim*Dh + k*Dh + (n%Dh)
__global__ __launch_bounds__(256) void transpose_all(
    const float* __restrict__ Wq, const float* __restrict__ Wk, const float* __restrict__ Wv,
    const float* __restrict__ Wo, const float* __restrict__ W1, const float* __restrict__ W2,
    __half* __restrict__ WQKV, __half* __restrict__ WTO,
    __half* __restrict__ WT1,  __half* __restrict__ WT2)
{
    int bid = blockIdx.x;
    const float* in; __half* out;
    int Kdim, Dh, nx;

    if (bid < 3456) {                       // Wq, Wk, Wv: 3 x 1152 blocks (48 x 24)
        const int j = bid / 1152; bid -= j * 1152;
        in  = (j == 0) ? Wq : (j == 1) ? Wk : Wv;
        out = WQKV + (size_t)j * CATD * EMBED;
        Kdim = EMBED; Dh = HEAD_DIM; nx = 48;
    } else if (bid < 4608) {                // Wo: 1152 blocks (24 x 48)
        bid -= 3456; in = Wo; out = WTO;
        Kdim = CATD; Dh = EMBED; nx = 24;
    } else if (bid < 6912) {                // W1: 2304 blocks (96 x 24)
        bid -= 4608; in = W1; out = WT1;
        Kdim = EMBED; Dh = FFN; nx = 96;
    } else {                                // W2: 2304 blocks (24 x 96)
        bid -= 6912; in = W2; out = WT2;
        Kdim = FFN; Dh = EMBED; nx = 24;
    }
    const int bx = bid % nx, by = bid / nx;

    __shared__ float t[32][33];
    const int k0 = by * 32;
    const int n0 = bx * 32;
    const int tx = threadIdx.x, ty = threadIdx.y;

    #pragma unroll
    for (int i = 0; i < 4; i++) {
        const int k = k0 + ty + 8 * i;
        const int n = n0 + tx;
        const int h = n / Dh, d = n - h * Dh;
        t[ty + 8 * i][tx] = in[(size_t)h * Kdim * Dh + (size_t)k * Dh + d];
    }
    __syncthreads();
    #pragma unroll
    for (int i = 0; i < 4; i++) {
        out[(size_t)(n0 + ty + 8 * i) * Kdim + k0 + tx] = __float2half_rn(t[tx][ty + 8 * i]);
    }
}

// ================= LayerNorm (fp32 in -> fp16 out) =================
__global__ __launch_bounds__(256) void layernorm_k(
    const float* __restrict__ x, __half* __restrict__ y,
    const float* __restrict__ g, const float* __restrict__ b)
{
    const int row = blockIdx.x;
    const int tid = threadIdx.x;
    const float* xr = x + (size_t)row * EMBED;

    float v0 = xr[tid];
    float v1 = xr[tid + 256];
    float v2 = xr[tid + 512];

    float s = v0 + v1 + v2;
    float q = v0 * v0 + v1 * v1 + v2 * v2;

    #pragma unroll
    for (int o = 16; o; o >>= 1) {
        s += __shfl_xor_sync(0xffffffffu, s, o);
        q += __shfl_xor_sync(0xffffffffu, q, o);
    }
    __shared__ float ss[8], sq[8];
    const int w = tid >> 5, l = tid & 31;
    if (l == 0) { ss[w] = s; sq[w] = q; }
    __syncthreads();
    float S = 0.f, Q = 0.f;
    #pragma unroll
    for (int i = 0; i < 8; i++) { S += ss[i]; Q += sq[i]; }

    const float mu  = S * (1.0f / EMBED);
    const float var = Q * (1.0f / EMBED) - mu * mu;
    const float inv = rsqrtf(var + 1e-5f);

    __half* yr = y + (size_t)row * EMBED;
    yr[tid]       = __float2half_rn((v0 - mu) * inv * g[tid]       + b[tid]);
    yr[tid + 256] = __float2half_rn((v1 - mu) * inv * g[tid + 256] + b[tid + 256]);
    yr[tid + 512] = __float2half_rn((v2 - mu) * inv * g[tid + 512] + b[tid + 512]);
}

// ================= GEMM (fp16, 3-stage cp.async, ldmatrix) =================
// C[m,n] = sum_k Hm[m,k]*Wt[n,k] (+bias)(relu)(+res fp32)
template<bool OUT16, bool BIAS, bool RELU, bool RES>
__global__ __launch_bounds__(256) void gemm_tc(
    const __half* __restrict__ Wt,   // [Nout, K]  K-major fp16
    const __half* __restrict__ Hm,   // [NTOK, K]  fp16
    void* __restrict__ Cout,         // fp16 or fp32 [NTOK, Nout]
    int K, int Nout,
    const float* __restrict__ bias,
    const float* __restrict__ res)
{
    extern __shared__ char smem[];
    const uint32_t sb32 = smem_u32(smem);

    const int tid = threadIdx.x;
    const int wid = tid >> 5, lid = tid & 31;
    const int g = lid >> 2, t = lid & 3;
    const int wm = wid & 3;
    const int wn = wid >> 2;

    const int n0 = blockIdx.x * TILE_NF;
    const int m0 = blockIdx.y * TILE_TK;
    const int chunks = K / KCH;

    const __half* Ag = Hm + (size_t)m0 * K;
    const __half* Bg = Wt + (size_t)n0 * K;

    const int arow = tid >> 3, aq = tid & 7;

    const uint32_t a_lane = (uint32_t)(((lid & 15) * HSTR + ((lid >> 4) << 3)) * 2);
    const uint32_t b_lane = (uint32_t)((((lid & 7) + ((lid >> 4) << 3)) * HSTR + ((lid >> 3) & 1) * 8) * 2);

    float acc[4][8][4];
    #pragma unroll
    for (int i = 0; i < 4; i++)
        #pragma unroll
        for (int j = 0; j < 8; j++)
            #pragma unroll
            for (int r = 0; r < 4; r++) acc[i][j][r] = 0.f;

    #define ISSUE_CHUNK(chunk, stg) do { \
        const int kofs_ = (chunk) * KCH; \
        const uint32_t sA_ = sb32 + (stg) * STG_B; \
        const uint32_t sB_ = sA_ + TILE_TK * HSTR * 2; \
        _Pragma("unroll") \
        for (int i = 0; i < 8; i++) \
            CP_ASYNC16(sA_ + (((arow + 32 * i) * HSTR + aq * 8) * 2), \
                       Ag + (size_t)(arow + 32 * i) * K + kofs_ + aq * 8); \
        _Pragma("unroll") \
        for (int i = 0; i < 4; i++) \
            CP_ASYNC16(sB_ + (((arow + 32 * i) * HSTR + aq * 8) * 2), \
                       Bg + (size_t)(arow + 32 * i) * K + kofs_ + aq * 8); \
    } while (0)

    ISSUE_CHUNK(0, 0); CP_COMMIT();
    if (chunks > 1) { ISSUE_CHUNK(1, 1); } CP_COMMIT();

    for (int c = 0; c < chunks; c++) {
        CP_WAIT1();
        __syncthreads();

        if (c + STAGES - 1 < chunks) { ISSUE_CHUNK(c + STAGES - 1, (c + STAGES - 1) % STAGES); }
        CP_COMMIT();

        const uint32_t sA32 = sb32 + (c % STAGES) * STG_B;
        const uint32_t sB32 = sA32 + TILE_TK * HSTR * 2;

        #pragma unroll
        for (int ks = 0; ks < 4; ks++) {
            const int kb = ks * 16;
            uint32_t af[4][4];
            #pragma unroll
            for (int mt = 0; mt < 4; mt++) {
                const uint32_t addr = sA32 + (uint32_t)(((wm * 64 + mt * 16) * HSTR + kb) * 2) + a_lane;
                LDSM_X4(af[mt][0], af[mt][1], af[mt][2], af[mt][3], addr);
            }
            uint32_t bf[8][2];
            #pragma unroll
            for (int ntp = 0; ntp < 4; ntp++) {
                const uint32_t addr = sB32 + (uint32_t)(((wn * 64 + ntp * 16) * HSTR + kb) * 2) + b_lane;
                LDSM_X4(bf[2 * ntp][0], bf[2 * ntp][1], bf[2 * ntp + 1][0], bf[2 * ntp + 1][1], addr);
            }
            #pragma unroll
            for (int mt = 0; mt < 4; mt++)
                #pragma unroll
                for (int nt = 0; nt < 8; nt++)
                    mma16816(acc[mt][nt], af[mt], bf[nt]);
        }
    }
    #undef ISSUE_CHUNK

    float* C32 = reinterpret_cast<float*>(Cout);
    __half* C16 = reinterpret_cast<__half*>(Cout);

    #pragma unroll
    for (int mt = 0; mt < 4; mt++) {
        #pragma unroll
        for (int nt = 0; nt < 8; nt++) {
            const int col = n0 + wn * 64 + nt * 8 + 2 * t;
            float bx = 0.f, by = 0.f;
            if (BIAS) {
                const float2 b2 = *reinterpret_cast<const float2*>(bias + col);
                bx = b2.x; by = b2.y;
            }
            const int r1 = m0 + wm * 64 + mt * 16 + g;
            const int r2 = r1 + 8;

            float2 v1, v2;
            v1.x = acc[mt][nt][0] + bx; v1.y = acc[mt][nt][1] + by;
            v2.x = acc[mt][nt][2] + bx; v2.y = acc[mt][nt][3] + by;
            if (RELU) {
                v1.x = fmaxf(v1.x, 0.f); v1.y = fmaxf(v1.y, 0.f);
                v2.x = fmaxf(v2.x, 0.f); v2.y = fmaxf(v2.y, 0.f);
            }
            if (RES) {
                const float2 r1v = *reinterpret_cast<const float2*>(res + (size_t)r1 * Nout + col);
                const float2 r2v = *reinterpret_cast<const float2*>(res + (size_t)r2 * Nout + col);
                v1.x += r1v.x; v1.y += r1v.y;
                v2.x += r2v.x; v2.y += r2v.y;
            }
            if (OUT16) {
                *reinterpret_cast<uint32_t*>(C16 + (size_t)r1 * Nout + col) = packh2(v1.x, v1.y);
                *reinterpret_cast<uint32_t*>(C16 + (size_t)r2 * Nout + col) = packh2(v2.x, v2.y);
            } else {
                *reinterpret_cast<float2*>(C32 + (size_t)r1 * Nout + col) = v1;
                *reinterpret_cast<float2*>(C32 + (size_t)r2 * Nout + col) = v2;
            }
        }
    }
}

// ================= tensor-core causal attention (single-load, 5 syncs) =================
#define PSTR  136
#define AQSTR 264   // Q/K row stride (halves): 256 + 8 pad
#define SSTR  132   // S row stride (floats)
#define VSTR  130   // V^T row stride (halves)
// bufA holds Q (128*AQSTR*2 = 67584 B) then V^T (256*VSTR*2 = 66560 B): size = max = 67584
#define BUFA_B  (128 * AQSTR * 2)
#define OFF_BUFA (128 * PSTR * 2)                  // 34816
#define OFF_BUFB (OFF_BUFA + BUFA_B)               // 102400
#define ATTN_SMEM (OFF_BUFB + 128 * SSTR * 4)      // 169984

__global__ __launch_bounds__(256) void attention_k(
    const __half* __restrict__ qkv,   // [NTOK][4608]
    __half* __restrict__ o)           // [NTOK][1536]
{
    extern __shared__ char smem[];
    uint16_t* sP  = reinterpret_cast<uint16_t*>(smem);
    uint16_t* sQ  = reinterpret_cast<uint16_t*>(smem + OFF_BUFA);   // later V^T
    uint16_t* sVt = sQ;
    uint16_t* sK  = reinterpret_cast<uint16_t*>(smem + OFF_BUFB);   // later S (fp32)
    float*    sS  = reinterpret_cast<float*>(smem + OFF_BUFB);

    const int tid = threadIdx.x;
    const int wid = tid >> 5, lid = tid & 31;
    const int g = lid >> 2, t = lid & 3;
    const int wm = wid & 3;
    const int wn = wid >> 2;

    const int bh = blockIdx.x;
    const int b  = bh / HEADS;
    const int h  = bh - b * HEADS;

    const __half* qbase = qkv + (size_t)(b * SEQ) * QKVD + h * HEAD_DIM;
    const __half* kbase = qbase + CATD;
    const __half* vbase = qbase + 2 * CATD;
    __half* obase = o + (size_t)(b * SEQ) * CATD + h * HEAD_DIM;

    // ---- phase 1: load full Q, K ----
    #pragma unroll
    for (int i = 0; i < 16; i++) {
        const int idx = tid + 256 * i;
        const int row = idx >> 5, q = idx & 31;
        *reinterpret_cast<uint4*>(sQ + row * AQSTR + q * 8) =
            *reinterpret_cast<const uint4*>(qbase + (size_t)row * QKVD + q * 8);
        *reinterpret_cast<uint4*>(sK + row * AQSTR + q * 8) =
            *reinterpret_cast<const uint4*>(kbase + (size_t)row * QKVD + q * 8);
    }
    __syncthreads();

    // ---- phase 2: S = Q K^T ----
    float acc[2][8][4];
    #pragma unroll
    for (int i = 0; i < 2; i++)
        #pragma unroll
        for (int j = 0; j < 8; j++)
            #pragma unroll
            for (int r = 0; r < 4; r++) acc[i][j][r] = 0.f;

    #pragma unroll
    for (int ks = 0; ks < 16; ks++) {
        const int kb = ks * 16;
        uint32_t af[2][4];
        #pragma unroll
        for (int mt = 0; mt < 2; mt++) {
            const int rb = wm * 32 + mt * 16;
            af[mt][0] = *reinterpret_cast<const uint32_t*>(&sQ[(rb + g)     * AQSTR + kb + 2 * t]);
            af[mt][1] = *reinterpret_cast<const uint32_t*>(&sQ[(rb + g + 8) * AQSTR + kb + 2 * t]);
            af[mt][2] = *reinterpret_cast<const uint32_t*>(&sQ[(rb + g)     * AQSTR + kb + 2 * t + 8]);
            af[mt][3] = *reinterpret_cast<const uint32_t*>(&sQ[(rb + g + 8) * AQSTR + kb + 2 * t + 8]);
        }
        #pragma unroll
        for (int nt = 0; nt < 8; nt++) {
            if (wn * 64 + nt * 8 <= wm * 32 + 31) {
                const int cb = wn * 64 + nt * 8 + g;
                uint32_t bf[2];
                bf[0] = *reinterpret_cast<const uint32_t*>(&sK[cb * AQSTR + kb + 2 * t]);
                bf[1] = *reinterpret_cast<const uint32_t*>(&sK[cb * AQSTR + kb + 2 * t + 8]);
                #pragma unroll
                for (int mt = 0; mt < 2; mt++)
                    mma16816(acc[mt][nt], af[mt], bf);
            }
        }
    }
    __syncthreads();

    // ---- phase 3: write scaled S + stage V^T ----
    const float scale = 0.03608439182435161f; // 768^-0.5
    #pragma unroll
    for (int mt = 0; mt < 2; mt++) {
        #pragma unroll
        for (int nt = 0; nt < 8; nt++) {
            const int col = wn * 64 + nt * 8 + 2 * t;
            const int r1 = wm * 32 + mt * 16 + g;
            float2 v1, v2;
            v1.x = acc[mt][nt][0] * scale; v1.y = acc[mt][nt][1] * scale;
            v2.x = acc[mt][nt][2] * scale; v2.y = acc[mt][nt][3] * scale;
            *reinterpret_cast<float2*>(sS + (r1)     * SSTR + col) = v1;
            *reinterpret_cast<float2*>(sS + (r1 + 8) * SSTR + col) = v2;
        }
    }
    #pragma unroll
    for (int i = 0; i < 64; i++) {
        const int id = tid + 256 * i;
        const int s = id >> 7, d2 = id & 127;
        const uint32_t v2 = *reinterpret_cast<const uint32_t*>(
            vbase + (size_t)s * QKVD + 2 * d2);
        sVt[(2 * d2)     * VSTR + s] = (uint16_t)(v2 & 0xffffu);
        sVt[(2 * d2 + 1) * VSTR + s] = (uint16_t)(v2 >> 16);
    }
    __syncthreads();

    // ---- phase 4: softmax (one warp per row) ----
    for (int rr = wid; rr < 128; rr += 8) {
        const float* row = sS + rr * SSTR;
        float mx = -1e30f;
        #pragma unroll
        for (int i = 0; i < 4; i++) {
            const int s = lid + 32 * i;
            if (s <= rr) mx = fmaxf(mx, row[s]);
        }
        #pragma unroll
        for (int o2 = 16; o2; o2 >>= 1) mx = fmaxf(mx, __shfl_xor_sync(0xffffffffu, mx, o2));

        float e[4];
        float sum = 0.f;
        #pragma unroll
        for (int i = 0; i < 4; i++) {
            const int s = lid + 32 * i;
            e[i] = (s <= rr) ? __expf(row[s] - mx) : 0.f;
            sum += e[i];
        }
        #pragma unroll
        for (int o2 = 16; o2; o2 >>= 1) sum += __shfl_xor_sync(0xffffffffu, sum, o2);
        const float inv = 1.0f / sum;

        uint16_t* prow = sP + rr * PSTR;
        #pragma unroll
        for (int i = 0; i < 4; i++) {
            const int s = lid + 32 * i;
            const __half hv = __float2half_rn(e[i] * inv);
            prow[s] = *reinterpret_cast<const uint16_t*>(&hv);
        }
    }
    __syncthreads();

    // ---- phase 5: O = P V ----
    #pragma unroll
    for (int c = 0; c < 4; c++) {
        float oacc[2][4][4];
        #pragma unroll
        for (int i = 0; i < 2; i++)
            #pragma unroll
            for (int j = 0; j < 4; j++)
                #pragma unroll
                for (int r = 0; r < 4; r++) oacc[i][j][r] = 0.f;

        #pragma unroll
        for (int ks = 0; ks < 8; ks++) {
            if (ks * 16 > wm * 32 + 31) break;
            const int kb = ks * 16;
            uint32_t af[2][4];
            #pragma unroll
            for (int mt = 0; mt < 2; mt++) {
                const int rb = wm * 32 + mt * 16;
                af[mt][0] = *reinterpret_cast<const uint32_t*>(&sP[(rb + g)     * PSTR + kb + 2 * t]);
                af[mt][1] = *reinterpret_cast<const uint32_t*>(&sP[(rb + g + 8) * PSTR + kb + 2 * t]);
                af[mt][2] = *reinterpret_cast<const uint32_t*>(&sP[(rb + g)     * PSTR + kb + 2 * t + 8]);
                af[mt][3] = *reinterpret_cast<const uint32_t*>(&sP[(rb + g + 8) * PSTR + kb + 2 * t + 8]);
            }
            #pragma unroll
            for (int nt = 0; nt < 4; nt++) {
                const int cb = c * 64 + wn * 32 + nt * 8 + g;
                uint32_t bf[2];
                bf[0] = *reinterpret_cast<const uint32_t*>(&sVt[cb * VSTR + kb + 2 * t]);
                bf[1] = *reinterpret_cast<const uint32_t*>(&sVt[cb * VSTR + kb + 2 * t + 8]);
                #pragma unroll
                for (int mt = 0; mt < 2; mt++)
                    mma16816(oacc[mt][nt], af[mt], bf);
            }
        }

        #pragma unroll
        for (int mt = 0; mt < 2; mt++) {
            #pragma unroll
            for (int nt = 0; nt < 4; nt++) {
                const int d = c * 64 + wn * 32 + nt * 8 + 2 * t;
                const int r1 = wm * 32 + mt * 16 + g;
                *reinterpret_cast<uint32_t*>(obase + (size_t)r1 * CATD + d) =
                    packh2(oacc[mt][nt][0], oacc[mt][nt][1]);
                *reinterpret_cast<uint32_t*>(obase + (size_t)(r1 + 8) * CATD + d) =
                    packh2(oacc[mt][nt][2], oacc[mt][nt][3]);
            }
        }
    }
}

// ================= launch =================
extern "C" void kernel_launch(void* const* d_in, const int* in_sizes, int n_in,
                              void* d_out, int out_size)
{
    const float* x   = (const float*)d_in[0];
    const float* Wq  = (const float*)d_in[1];
    const float* Wk  = (const float*)d_in[2];
    const float* Wv  = (const float*)d_in[3];
    const float* Wo  = (const float*)d_in[4];
    const float* bo  = (const float*)d_in[5];
    const float* W1  = (const float*)d_in[6];
    const float* b1  = (const float*)d_in[7];
    const float* W2  = (const float*)d_in[8];
    const float* b2  = (const float*)d_in[9];
    const float* g1  = (const float*)d_in[10];
    const float* be1 = (const float*)d_in[11];
    const float* g2  = (const float*)d_in[12];
    const float* be2 = (const float*)d_in[13];
    float* out = (float*)d_out;

    void *phh, *pqkv, *poh, *pres, *pmid, *pwqkv, *pwto, *pwt1, *pwt2;
    cudaGetSymbolAddress(&phh,  g_hh);
    cudaGetSymbolAddress(&pqkv, g_qkv);
    cudaGetSymbolAddress(&poh,  g_oh);
    cudaGetSymbolAddress(&pres, g_res);
    cudaGetSymbolAddress(&pmid, g_mid);
    cudaGetSymbolAddress(&pwqkv, g_wqkv);
    cudaGetSymbolAddress(&pwto, g_wto);
    cudaGetSymbolAddress(&pwt1, g_wt1);
    cudaGetSymbolAddress(&pwt2, g_wt2);
    __half* H    = (__half*)phh;
    __half* QKV  = (__half*)pqkv;
    __half* O    = (__half*)poh;
    float*  R    = (float*)pres;
    __half* MID  = (__half*)pmid;
    __half* WQKV = (__half*)pwqkv;
    __half* WTO  = (__half*)pwto;
    __half* WT1  = (__half*)pwt1;
    __half* WT2  = (__half*)pwt2;

    cudaFuncSetAttribute(attention_k, cudaFuncAttributeMaxDynamicSharedMemorySize, ATTN_SMEM);
    cudaFuncSetAttribute(gemm_tc<true,  false, false, false>, cudaFuncAttributeMaxDynamicSharedMemorySize, GEMM_SMEM);
    cudaFuncSetAttribute(gemm_tc<false, true,  false, true >, cudaFuncAttributeMaxDynamicSharedMemorySize, GEMM_SMEM);
    cudaFuncSetAttribute(gemm_tc<true,  true,  true,  false>, cudaFuncAttributeMaxDynamicSharedMemorySize, GEMM_SMEM);

    // all 6 weight transposes in ONE launch: 3456 (QKV) + 1152 (Wo) + 2304 (W1) + 2304 (W2) = 9216
    transpose_all<<<9216, dim3(32, 8)>>>(Wq, Wk, Wv, Wo, W1, W2, WQKV, WTO, WT1, WT2);

    // LN1
    layernorm_k<<<NTOK, 256>>>(x, H, g1, be1);

    // fused QKV projection -> fp16
    gemm_tc<true, false, false, false><<<dim3(QKVD / TILE_NF, NTOK / TILE_TK), 256, GEMM_SMEM>>>(
        WQKV, H, QKV, EMBED, QKVD, nullptr, nullptr);

    // attention
    attention_k<<<BATCH * HEADS, 256, ATTN_SMEM>>>(QKV, O);

    // attn_out = O @ Wo + bo + x  -> fp32 R
    gemm_tc<false, true, false, true><<<dim3(EMBED / TILE_NF, NTOK / TILE_TK), 256, GEMM_SMEM>>>(
        WTO, O, R, CATD, EMBED, bo, x);

    // LN2
    layernorm_k<<<NTOK, 256>>>(R, H, g2, be2);

    // MID = relu(H @ W1 + b1)  (fp16)
    gemm_tc<true, true, true, false><<<dim3(FFN / TILE_NF, NTOK / TILE_TK), 256, GEMM_SMEM>>>(
        WT1, H, MID, EMBED, FFN, b1, nullptr);

    // out = MID @ W2 + b2 + R  (fp32)
    gemm_tc<false, true, false, true><<<dim3(EMBED / TILE_NF, NTOK / TILE_TK), 256, GEMM_SMEM>>>(
        WT2, MID, out, FFN, EMBED, b2, R);
}

// round 17
// speedup vs baseline: 1.0158x; 1.0055x over previous
#include <cuda_runtime.h>
#include <cuda_fp16.h>
#include <cstdint>

#define EMBED    768
#define HEADS    6
#define HEAD_DIM 256
#define SEQ      128
#define BATCH    512
#define NTOK     (BATCH * SEQ)        // 65536
#define CATD     (HEADS * HEAD_DIM)   // 1536
#define QKVD     (3 * CATD)           // 4608
#define FFN      (4 * EMBED)          // 3072

// ================= helpers =================
__device__ __forceinline__ uint32_t packh2(float lo, float hi) {
    uint32_t r;
    asm("cvt.rn.f16x2.f32 %0, %1, %2;" : "=r"(r) : "f"(hi), "f"(lo));
    return r;
}
__device__ __forceinline__ void mma16816(float* c, const uint32_t* a, const uint32_t* b) {
    asm volatile(
        "mma.sync.aligned.m16n8k16.row.col.f32.f16.f16.f32 "
        "{%0,%1,%2,%3}, {%4,%5,%6,%7}, {%8,%9}, {%0,%1,%2,%3};"
        : "+f"(c[0]), "+f"(c[1]), "+f"(c[2]), "+f"(c[3])
        : "r"(a[0]), "r"(a[1]), "r"(a[2]), "r"(a[3]), "r"(b[0]), "r"(b[1]));
}
__device__ __forceinline__ uint32_t smem_u32(const void* p) {
    uint32_t a;
    asm("{ .reg .u64 t; cvta.to.shared.u64 t, %1; cvt.u32.u64 %0, t; }" : "=r"(a) : "l"(p));
    return a;
}
#define CP_ASYNC16(saddr, gptr) \
    asm volatile("cp.async.cg.shared.global [%0], [%1], 16;" :: "r"(saddr), "l"(gptr))
#define CP_COMMIT() asm volatile("cp.async.commit_group;" ::: "memory")
#define CP_WAIT1()  asm volatile("cp.async.wait_group 1;" ::: "memory")
#define CP_WAIT0()  asm volatile("cp.async.wait_group 0;" ::: "memory")
#define LDSM_X4(r0, r1, r2, r3, addr) \
    asm volatile("ldmatrix.sync.aligned.m8n8.x4.shared.b16 {%0,%1,%2,%3}, [%4];" \
        : "=r"(r0), "=r"(r1), "=r"(r2), "=r"(r3) : "r"(addr))

// GEMM tiling (R9/R10-proven config: 3 stages, wait_group 1, KCH=64, ldmatrix)
#define TILE_NF  128
#define TILE_TK  256
#define KCH      64
#define HSTR     72
#define STAGES   3
#define STG_H    ((TILE_TK + TILE_NF) * HSTR)
#define STG_B    (STG_H * 2)                           // 55296
#define GEMM_SMEM (STAGES * STG_B)                     // 165888

// ================= scratch =================
__device__ __half g_hh  [(size_t)NTOK * EMBED];
__device__ __half g_qkv [(size_t)NTOK * QKVD];
__device__ __half g_oh  [(size_t)NTOK * CATD];
__device__ float  g_res [(size_t)NTOK * EMBED];
__device__ __half g_mid [(size_t)NTOK * FFN];
__device__ __half g_wqkv[(size_t)QKVD * EMBED];
__device__ __half g_wto [(size_t)EMBED * CATD];
__device__ __half g_wt1 [(size_t)FFN * EMBED];
__device__ __half g_wt2 [(size_t)EMBED * FFN];

// ================= fused transpose: all 6 weights in ONE launch (9216 blocks) =================
__global__ __launch_bounds__(256) void transpose_all(
    const float* __restrict__ Wq, const float* __restrict__ Wk, const float* __restrict__ Wv,
    const float* __restrict__ Wo, const float* __restrict__ W1, const float* __restrict__ W2,
    __half* __restrict__ WQKV, __half* __restrict__ WTO,
    __half* __restrict__ WT1,  __half* __restrict__ WT2)
{
    int bid = blockIdx.x;
    const float* in; __half* out;
    int Kdim, Dh, nx;

    if (bid < 3456) {                       // Wq, Wk, Wv: 3 x 1152 blocks (48 x 24)
        const int j = bid / 1152; bid -= j * 1152;
        in  = (j == 0) ? Wq : (j == 1) ? Wk : Wv;
        out = WQKV + (size_t)j * CATD * EMBED;
        Kdim = EMBED; Dh = HEAD_DIM; nx = 48;
    } else if (bid < 4608) {                // Wo: 1152 blocks (24 x 48)
        bid -= 3456; in = Wo; out = WTO;
        Kdim = CATD; Dh = EMBED; nx = 24;
    } else if (bid < 6912) {                // W1: 2304 blocks (96 x 24)
        bid -= 4608; in = W1; out = WT1;
        Kdim = EMBED; Dh = FFN; nx = 96;
    } else {                                // W2: 2304 blocks (24 x 96)
        bid -= 6912; in = W2; out = WT2;
        Kdim = FFN; Dh = EMBED; nx = 24;
    }
    const int bx = bid % nx, by = bid / nx;

    __shared__ float t[32][33];
    const int k0 = by * 32;
    const int n0 = bx * 32;
    const int tx = threadIdx.x, ty = threadIdx.y;

    #pragma unroll
    for (int i = 0; i < 4; i++) {
        const int k = k0 + ty + 8 * i;
        const int n = n0 + tx;
        const int h = n / Dh, d = n - h * Dh;
        t[ty + 8 * i][tx] = in[(size_t)h * Kdim * Dh + (size_t)k * Dh + d];
    }
    __syncthreads();
    #pragma unroll
    for (int i = 0; i < 4; i++) {
        out[(size_t)(n0 + ty + 8 * i) * Kdim + k0 + tx] = __float2half_rn(t[tx][ty + 8 * i]);
    }
}

// ================= LayerNorm (fp32 in -> fp16 out) =================
__global__ __launch_bounds__(256) void layernorm_k(
    const float* __restrict__ x, __half* __restrict__ y,
    const float* __restrict__ g, const float* __restrict__ b)
{
    const int row = blockIdx.x;
    const int tid = threadIdx.x;
    const float* xr = x + (size_t)row * EMBED;

    float v0 = xr[tid];
    float v1 = xr[tid + 256];
    float v2 = xr[tid + 512];

    float s = v0 + v1 + v2;
    float q = v0 * v0 + v1 * v1 + v2 * v2;

    #pragma unroll
    for (int o = 16; o; o >>= 1) {
        s += __shfl_xor_sync(0xffffffffu, s, o);
        q += __shfl_xor_sync(0xffffffffu, q, o);
    }
    __shared__ float ss[8], sq[8];
    const int w = tid >> 5, l = tid & 31;
    if (l == 0) { ss[w] = s; sq[w] = q; }
    __syncthreads();
    float S = 0.f, Q = 0.f;
    #pragma unroll
    for (int i = 0; i < 8; i++) { S += ss[i]; Q += sq[i]; }

    const float mu  = S * (1.0f / EMBED);
    const float var = Q * (1.0f / EMBED) - mu * mu;
    const float inv = rsqrtf(var + 1e-5f);

    __half* yr = y + (size_t)row * EMBED;
    yr[tid]       = __float2half_rn((v0 - mu) * inv * g[tid]       + b[tid]);
    yr[tid + 256] = __float2half_rn((v1 - mu) * inv * g[tid + 256] + b[tid + 256]);
    yr[tid + 512] = __float2half_rn((v2 - mu) * inv * g[tid + 512] + b[tid + 512]);
}

// ================= GEMM (fp16, 3-stage cp.async, ldmatrix) =================
template<bool OUT16, bool BIAS, bool RELU, bool RES>
__global__ __launch_bounds__(256) void gemm_tc(
    const __half* __restrict__ Wt,   // [Nout, K]  K-major fp16
    const __half* __restrict__ Hm,   // [NTOK, K]  fp16
    void* __restrict__ Cout,         // fp16 or fp32 [NTOK, Nout]
    int K, int Nout,
    const float* __restrict__ bias,
    const float* __restrict__ res)
{
    extern __shared__ char smem[];
    const uint32_t sb32 = smem_u32(smem);

    const int tid = threadIdx.x;
    const int wid = tid >> 5, lid = tid & 31;
    const int g = lid >> 2, t = lid & 3;
    const int wm = wid & 3;
    const int wn = wid >> 2;

    const int n0 = blockIdx.x * TILE_NF;
    const int m0 = blockIdx.y * TILE_TK;
    const int chunks = K / KCH;

    const __half* Ag = Hm + (size_t)m0 * K;
    const __half* Bg = Wt + (size_t)n0 * K;

    const int arow = tid >> 3, aq = tid & 7;

    const uint32_t a_lane = (uint32_t)(((lid & 15) * HSTR + ((lid >> 4) << 3)) * 2);
    const uint32_t b_lane = (uint32_t)((((lid & 7) + ((lid >> 4) << 3)) * HSTR + ((lid >> 3) & 1) * 8) * 2);

    float acc[4][8][4];
    #pragma unroll
    for (int i = 0; i < 4; i++)
        #pragma unroll
        for (int j = 0; j < 8; j++)
            #pragma unroll
            for (int r = 0; r < 4; r++) acc[i][j][r] = 0.f;

    #define ISSUE_CHUNK(chunk, stg) do { \
        const int kofs_ = (chunk) * KCH; \
        const uint32_t sA_ = sb32 + (stg) * STG_B; \
        const uint32_t sB_ = sA_ + TILE_TK * HSTR * 2; \
        _Pragma("unroll") \
        for (int i = 0; i < 8; i++) \
            CP_ASYNC16(sA_ + (((arow + 32 * i) * HSTR + aq * 8) * 2), \
                       Ag + (size_t)(arow + 32 * i) * K + kofs_ + aq * 8); \
        _Pragma("unroll") \
        for (int i = 0; i < 4; i++) \
            CP_ASYNC16(sB_ + (((arow + 32 * i) * HSTR + aq * 8) * 2), \
                       Bg + (size_t)(arow + 32 * i) * K + kofs_ + aq * 8); \
    } while (0)

    ISSUE_CHUNK(0, 0); CP_COMMIT();
    if (chunks > 1) { ISSUE_CHUNK(1, 1); } CP_COMMIT();

    for (int c = 0; c < chunks; c++) {
        CP_WAIT1();
        __syncthreads();

        if (c + STAGES - 1 < chunks) { ISSUE_CHUNK(c + STAGES - 1, (c + STAGES - 1) % STAGES); }
        CP_COMMIT();

        const uint32_t sA32 = sb32 + (c % STAGES) * STG_B;
        const uint32_t sB32 = sA32 + TILE_TK * HSTR * 2;

        #pragma unroll
        for (int ks = 0; ks < 4; ks++) {
            const int kb = ks * 16;
            uint32_t af[4][4];
            #pragma unroll
            for (int mt = 0; mt < 4; mt++) {
                const uint32_t addr = sA32 + (uint32_t)(((wm * 64 + mt * 16) * HSTR + kb) * 2) + a_lane;
                LDSM_X4(af[mt][0], af[mt][1], af[mt][2], af[mt][3], addr);
            }
            uint32_t bf[8][2];
            #pragma unroll
            for (int ntp = 0; ntp < 4; ntp++) {
                const uint32_t addr = sB32 + (uint32_t)(((wn * 64 + ntp * 16) * HSTR + kb) * 2) + b_lane;
                LDSM_X4(bf[2 * ntp][0], bf[2 * ntp][1], bf[2 * ntp + 1][0], bf[2 * ntp + 1][1], addr);
            }
            #pragma unroll
            for (int mt = 0; mt < 4; mt++)
                #pragma unroll
                for (int nt = 0; nt < 8; nt++)
                    mma16816(acc[mt][nt], af[mt], bf[nt]);
        }
    }
    #undef ISSUE_CHUNK

    float* C32 = reinterpret_cast<float*>(Cout);
    __half* C16 = reinterpret_cast<__half*>(Cout);

    #pragma unroll
    for (int mt = 0; mt < 4; mt++) {
        #pragma unroll
        for (int nt = 0; nt < 8; nt++) {
            const int col = n0 + wn * 64 + nt * 8 + 2 * t;
            float bx = 0.f, by = 0.f;
            if (BIAS) {
                const float2 b2 = *reinterpret_cast<const float2*>(bias + col);
                bx = b2.x; by = b2.y;
            }
            const int r1 = m0 + wm * 64 + mt * 16 + g;
            const int r2 = r1 + 8;

            float2 v1, v2;
            v1.x = acc[mt][nt][0] + bx; v1.y = acc[mt][nt][1] + by;
            v2.x = acc[mt][nt][2] + bx; v2.y = acc[mt][nt][3] + by;
            if (RELU) {
                v1.x = fmaxf(v1.x, 0.f); v1.y = fmaxf(v1.y, 0.f);
                v2.x = fmaxf(v2.x, 0.f); v2.y = fmaxf(v2.y, 0.f);
            }
            if (RES) {
                const float2 r1v = *reinterpret_cast<const float2*>(res + (size_t)r1 * Nout + col);
                const float2 r2v = *reinterpret_cast<const float2*>(res + (size_t)r2 * Nout + col);
                v1.x += r1v.x; v1.y += r1v.y;
                v2.x += r2v.x; v2.y += r2v.y;
            }
            if (OUT16) {
                *reinterpret_cast<uint32_t*>(C16 + (size_t)r1 * Nout + col) = packh2(v1.x, v1.y);
                *reinterpret_cast<uint32_t*>(C16 + (size_t)r2 * Nout + col) = packh2(v2.x, v2.y);
            } else {
                *reinterpret_cast<float2*>(C32 + (size_t)r1 * Nout + col) = v1;
                *reinterpret_cast<float2*>(C32 + (size_t)r2 * Nout + col) = v2;
            }
        }
    }
}

// ================= tensor-core causal attention (cp.async QK, V reg-prefetch) =================
#define PSTR  136
#define AQSTR 264   // Q/K row stride (halves): 256 + 8 pad
#define SSTR  132   // S row stride (floats)
#define VSTR  130   // V^T row stride (halves)
#define BUFA_B  (128 * AQSTR * 2)                  // 67584
#define OFF_BUFA (128 * PSTR * 2)                  // 34816
#define OFF_BUFB (OFF_BUFA + BUFA_B)               // 102400
#define ATTN_SMEM (OFF_BUFB + 128 * SSTR * 4)      // 169984

__global__ __launch_bounds__(256) void attention_k(
    const __half* __restrict__ qkv,   // [NTOK][4608]
    __half* __restrict__ o)           // [NTOK][1536]
{
    extern __shared__ char smem[];
    const uint32_t sb = smem_u32(smem);
    uint16_t* sP  = reinterpret_cast<uint16_t*>(smem);
    uint16_t* sQ  = reinterpret_cast<uint16_t*>(smem + OFF_BUFA);   // later V^T
    uint16_t* sVt = sQ;
    uint16_t* sK  = reinterpret_cast<uint16_t*>(smem + OFF_BUFB);   // later S (fp32)
    float*    sS  = reinterpret_cast<float*>(smem + OFF_BUFB);

    const int tid = threadIdx.x;
    const int wid = tid >> 5, lid = tid & 31;
    const int g = lid >> 2, t = lid & 3;
    const int wm = wid & 3;
    const int wn = wid >> 2;

    const int bh = blockIdx.x;
    const int b  = bh / HEADS;
    const int h  = bh - b * HEADS;

    const __half* qbase = qkv + (size_t)(b * SEQ) * QKVD + h * HEAD_DIM;
    const __half* kbase = qbase + CATD;
    const __half* vbase = qbase + 2 * CATD;
    __half* obase = o + (size_t)(b * SEQ) * CATD + h * HEAD_DIM;

    // ---- phase 1a: issue Q, K loads via cp.async (no register staging) ----
    #pragma unroll
    for (int i = 0; i < 16; i++) {
        const int idx = tid + 256 * i;
        const int row = idx >> 5, q = idx & 31;
        CP_ASYNC16(sb + OFF_BUFA + (uint32_t)((row * AQSTR + q * 8) * 2),
                   qbase + (size_t)row * QKVD + q * 8);
        CP_ASYNC16(sb + OFF_BUFB + (uint32_t)((row * AQSTR + q * 8) * 2),
                   kbase + (size_t)row * QKVD + q * 8);
    }
    CP_COMMIT();

    // ---- phase 1b: prefetch V into registers (latency hidden under S-MMA) ----
    // id = tid + 256*i covers 16384 half2: s = id >> 7 in [0,128), d2 = id & 127 in [0,128)
    uint32_t vreg[64];
    #pragma unroll
    for (int i = 0; i < 64; i++) {
        const int id = tid + 256 * i;
        const int s = id >> 7, d2 = id & 127;
        vreg[i] = *reinterpret_cast<const uint32_t*>(vbase + (size_t)s * QKVD + 2 * d2);
    }

    CP_WAIT0();
    __syncthreads();

    // ---- phase 2: S = Q K^T ----
    float acc[2][8][4];
    #pragma unroll
    for (int i = 0; i < 2; i++)
        #pragma unroll
        for (int j = 0; j < 8; j++)
            #pragma unroll
            for (int r = 0; r < 4; r++) acc[i][j][r] = 0.f;

    #pragma unroll
    for (int ks = 0; ks < 16; ks++) {
        const int kb = ks * 16;
        uint32_t af[2][4];
        #pragma unroll
        for (int mt = 0; mt < 2; mt++) {
            const int rb = wm * 32 + mt * 16;
            af[mt][0] = *reinterpret_cast<const uint32_t*>(&sQ[(rb + g)     * AQSTR + kb + 2 * t]);
            af[mt][1] = *reinterpret_cast<const uint32_t*>(&sQ[(rb + g + 8) * AQSTR + kb + 2 * t]);
            af[mt][2] = *reinterpret_cast<const uint32_t*>(&sQ[(rb + g)     * AQSTR + kb + 2 * t + 8]);
            af[mt][3] = *reinterpret_cast<const uint32_t*>(&sQ[(rb + g + 8) * AQSTR + kb + 2 * t + 8]);
        }
        #pragma unroll
        for (int nt = 0; nt < 8; nt++) {
            if (wn * 64 + nt * 8 <= wm * 32 + 31) {
                const int cb = wn * 64 + nt * 8 + g;
                uint32_t bf[2];
                bf[0] = *reinterpret_cast<const uint32_t*>(&sK[cb * AQSTR + kb + 2 * t]);
                bf[1] = *reinterpret_cast<const uint32_t*>(&sK[cb * AQSTR + kb + 2 * t + 8]);
                #pragma unroll
                for (int mt = 0; mt < 2; mt++)
                    mma16816(acc[mt][nt], af[mt], bf);
            }
        }
    }
    __syncthreads();

    // ---- phase 3: write scaled S (bufB) + store prefetched V^T (bufA) ----
    const float scale = 0.03608439182435161f; // 768^-0.5
    #pragma unroll
    for (int mt = 0; mt < 2; mt++) {
        #pragma unroll
        for (int nt = 0; nt < 8; nt++) {
            const int col = wn * 64 + nt * 8 + 2 * t;
            const int r1 = wm * 32 + mt * 16 + g;
            float2 v1, v2;
            v1.x = acc[mt][nt][0] * scale; v1.y = acc[mt][nt][1] * scale;
            v2.x = acc[mt][nt][2] * scale; v2.y = acc[mt][nt][3] * scale;
            *reinterpret_cast<float2*>(sS + (r1)     * SSTR + col) = v1;
            *reinterpret_cast<float2*>(sS + (r1 + 8) * SSTR + col) = v2;
        }
    }
    #pragma unroll
    for (int i = 0; i < 64; i++) {
        const int id = tid + 256 * i;
        const int s = id >> 7, d2 = id & 127;
        sVt[(2 * d2)     * VSTR + s] = (uint16_t)(vreg[i] & 0xffffu);
        sVt[(2 * d2 + 1) * VSTR + s] = (uint16_t)(vreg[i] >> 16);
    }
    __syncthreads();

    // ---- phase 4: softmax (one warp per row) ----
    for (int rr = wid; rr < 128; rr += 8) {
        const float* row = sS + rr * SSTR;
        float mx = -1e30f;
        #pragma unroll
        for (int i = 0; i < 4; i++) {
            const int s = lid + 32 * i;
            if (s <= rr) mx = fmaxf(mx, row[s]);
        }
        #pragma unroll
        for (int o2 = 16; o2; o2 >>= 1) mx = fmaxf(mx, __shfl_xor_sync(0xffffffffu, mx, o2));

        float e[4];
        float sum = 0.f;
        #pragma unroll
        for (int i = 0; i < 4; i++) {
            const int s = lid + 32 * i;
            e[i] = (s <= rr) ? __expf(row[s] - mx) : 0.f;
            sum += e[i];
        }
        #pragma unroll
        for (int o2 = 16; o2; o2 >>= 1) sum += __shfl_xor_sync(0xffffffffu, sum, o2);
        const float inv = 1.0f / sum;

        uint16_t* prow = sP + rr * PSTR;
        #pragma unroll
        for (int i = 0; i < 4; i++) {
            const int s = lid + 32 * i;
            const __half hv = __float2half_rn(e[i] * inv);
            prow[s] = *reinterpret_cast<const uint16_t*>(&hv);
        }
    }
    __syncthreads();

    // ---- phase 5: O = P V ----
    #pragma unroll
    for (int c = 0; c < 4; c++) {
        float oacc[2][4][4];
        #pragma unroll
        for (int i = 0; i < 2; i++)
            #pragma unroll
            for (int j = 0; j < 4; j++)
                #pragma unroll
                for (int r = 0; r < 4; r++) oacc[i][j][r] = 0.f;

        #pragma unroll
        for (int ks = 0; ks < 8; ks++) {
            if (ks * 16 > wm * 32 + 31) break;
            const int kb = ks * 16;
            uint32_t af[2][4];
            #pragma unroll
            for (int mt = 0; mt < 2; mt++) {
                const int rb = wm * 32 + mt * 16;
                af[mt][0] = *reinterpret_cast<const uint32_t*>(&sP[(rb + g)     * PSTR + kb + 2 * t]);
                af[mt][1] = *reinterpret_cast<const uint32_t*>(&sP[(rb + g + 8) * PSTR + kb + 2 * t]);
                af[mt][2] = *reinterpret_cast<const uint32_t*>(&sP[(rb + g)     * PSTR + kb + 2 * t + 8]);
                af[mt][3] = *reinterpret_cast<const uint32_t*>(&sP[(rb + g + 8) * PSTR + kb + 2 * t + 8]);
            }
            #pragma unroll
            for (int nt = 0; nt < 4; nt++) {
                const int cb = c * 64 + wn * 32 + nt * 8 + g;
                uint32_t bf[2];
                bf[0] = *reinterpret_cast<const uint32_t*>(&sVt[cb * VSTR + kb + 2 * t]);
                bf[1] = *reinterpret_cast<const uint32_t*>(&sVt[cb * VSTR + kb + 2 * t + 8]);
                #pragma unroll
                for (int mt = 0; mt < 2; mt++)
                    mma16816(oacc[mt][nt], af[mt], bf);
            }
        }

        #pragma unroll
        for (int mt = 0; mt < 2; mt++) {
            #pragma unroll
            for (int nt = 0; nt < 4; nt++) {
                const int d = c * 64 + wn * 32 + nt * 8 + 2 * t;
                const int r1 = wm * 32 + mt * 16 + g;
                *reinterpret_cast<uint32_t*>(obase + (size_t)r1 * CATD + d) =
                    packh2(oacc[mt][nt][0], oacc[mt][nt][1]);
                *reinterpret_cast<uint32_t*>(obase + (size_t)(r1 + 8) * CATD + d) =
                    packh2(oacc[mt][nt][2], oacc[mt][nt][3]);
            }
        }
    }
}

// ================= launch =================
extern "C" void kernel_launch(void* const* d_in, const int* in_sizes, int n_in,
                              void* d_out, int out_size)
{
    const float* x   = (const float*)d_in[0];
    const float* Wq  = (const float*)d_in[1];
    const float* Wk  = (const float*)d_in[2];
    const float* Wv  = (const float*)d_in[3];
    const float* Wo  = (const float*)d_in[4];
    const float* bo  = (const float*)d_in[5];
    const float* W1  = (const float*)d_in[6];
    const float* b1  = (const float*)d_in[7];
    const float* W2  = (const float*)d_in[8];
    const float* b2  = (const float*)d_in[9];
    const float* g1  = (const float*)d_in[10];
    const float* be1 = (const float*)d_in[11];
    const float* g2  = (const float*)d_in[12];
    const float* be2 = (const float*)d_in[13];
    float* out = (float*)d_out;

    void *phh, *pqkv, *poh, *pres, *pmid, *pwqkv, *pwto, *pwt1, *pwt2;
    cudaGetSymbolAddress(&phh,  g_hh);
    cudaGetSymbolAddress(&pqkv, g_qkv);
    cudaGetSymbolAddress(&poh,  g_oh);
    cudaGetSymbolAddress(&pres, g_res);
    cudaGetSymbolAddress(&pmid, g_mid);
    cudaGetSymbolAddress(&pwqkv, g_wqkv);
    cudaGetSymbolAddress(&pwto, g_wto);
    cudaGetSymbolAddress(&pwt1, g_wt1);
    cudaGetSymbolAddress(&pwt2, g_wt2);
    __half* H    = (__half*)phh;
    __half* QKV  = (__half*)pqkv;
    __half* O    = (__half*)poh;
    float*  R    = (float*)pres;
    __half* MID  = (__half*)pmid;
    __half* WQKV = (__half*)pwqkv;
    __half* WTO  = (__half*)pwto;
    __half* WT1  = (__half*)pwt1;
    __half* WT2  = (__half*)pwt2;

    cudaFuncSetAttribute(attention_k, cudaFuncAttributeMaxDynamicSharedMemorySize, ATTN_SMEM);
    cudaFuncSetAttribute(gemm_tc<true,  false, false, false>, cudaFuncAttributeMaxDynamicSharedMemorySize, GEMM_SMEM);
    cudaFuncSetAttribute(gemm_tc<false, true,  false, true >, cudaFuncAttributeMaxDynamicSharedMemorySize, GEMM_SMEM);
    cudaFuncSetAttribute(gemm_tc<true,  true,  true,  false>, cudaFuncAttributeMaxDynamicSharedMemorySize, GEMM_SMEM);

    // all 6 weight transposes in ONE launch: 3456 + 1152 + 2304 + 2304 = 9216
    transpose_all<<<9216, dim3(32, 8)>>>(Wq, Wk, Wv, Wo, W1, W2, WQKV, WTO, WT1, WT2);

    // LN1
    layernorm_k<<<NTOK, 256>>>(x, H, g1, be1);

    // fused QKV projection -> fp16
    gemm_tc<true, false, false, false><<<dim3(QKVD / TILE_NF, NTOK / TILE_TK), 256, GEMM_SMEM>>>(
        WQKV, H, QKV, EMBED, QKVD, nullptr, nullptr);

    // attention
    attention_k<<<BATCH * HEADS, 256, ATTN_SMEM>>>(QKV, O);

    // attn_out = O @ Wo + bo + x  -> fp32 R
    gemm_tc<false, true, false, true><<<dim3(EMBED / TILE_NF, NTOK / TILE_TK), 256, GEMM_SMEM>>>(
        WTO, O, R, CATD, EMBED, bo, x);

    // LN2
    layernorm_k<<<NTOK, 256>>>(R, H, g2, be2);

    // MID = relu(H @ W1 + b1)  (fp16)
    gemm_tc<true, true, true, false><<<dim3(FFN / TILE_NF, NTOK / TILE_TK), 256, GEMM_SMEM>>>(
        WT1, H, MID, EMBED, FFN, b1, nullptr);

    // out = MID @ W2 + b2 + R  (fp32)
    gemm_tc<false, true, false, true><<<dim3(EMBED / TILE_NF, NTOK / TILE_TK), 256, GEMM_SMEM>>>(
        WT2, MID, out, FFN, EMBED, b2, R);
}